// round 1
// baseline (speedup 1.0000x reference)
#include <cuda_runtime.h>
#include <cstdint>

// ---------------------------------------------------------------------------
// QRNN 2-bit: ternary everything. Integer event-driven implementation.
// Shapes: V=30000, E=H=1024, L=2, O=4, B=64, T=512.
// ---------------------------------------------------------------------------

#define Ed 1024
#define Hd 1024
#define Bd 64
#define Td 512
#define Ld 2
#define Od 4
#define VCAP 32768

// -------- device scratch (allocation-free rule: __device__ globals) --------
__device__ unsigned int       g_maxbits;
__device__ float              g_scale;
__device__ int                g_is64;            // text dtype: 1 = int64, 0 = int32
__device__ float              g_rowmax[VCAP];
__device__ int8_t             g_siT0[Ed * Hd];   // sign(ternary(W_ih[0]))^T : [e][h]
__device__ int8_t             g_siT1[Hd * Hd];   // sign(ternary(W_ih[1]))^T : [e][h]
__device__ int8_t             g_shT0[Hd * Hd];   // sign(ternary(W_hh[0]))^T : [j][h]
__device__ int8_t             g_shT1[Hd * Hd];
__device__ short              g_xw0[(size_t)Bd * Td * Hd];  // layer-0 input rows (int counts)
__device__ short              g_xw1[(size_t)Bd * Td * Hd];  // layer-1 input rows
__device__ unsigned long long g_flags0[Bd * 8];  // per-(b) 512-bit event masks
__device__ unsigned long long g_flags1[Bd * 8];
__device__ int8_t             g_hlast[Ld * Bd * Hd];

// ---------------------------------------------------------------------------
// k_init: zero flags0 / maxbits, detect text dtype (int64 high words all 0).
// ---------------------------------------------------------------------------
__global__ void k_init(const int* __restrict__ textw)
{
    int i = threadIdx.x;
    if (i < Bd * 8) g_flags0[i] = 0ull;
    __shared__ int s_any;
    if (i == 0) { g_maxbits = 0u; s_any = 0; }
    __syncthreads();
    // If text is int64, words 1,3,5,... are high words == 0 (ids < 2^31).
    // If int32, they are token ids; all-zero over 64 samples is ~impossible.
    if (i < 64 && textw[2 * i + 1] != 0) s_any = 1;
    __syncthreads();
    if (i == 0) g_is64 = (s_any == 0) ? 1 : 0;
}

// ---------------------------------------------------------------------------
// k_rowmax: per-vocab-row max|emb| + global max. One block per row.
// ---------------------------------------------------------------------------
__global__ void __launch_bounds__(256) k_rowmax(const float* __restrict__ emb)
{
    int v = blockIdx.x;
    const float4* row = reinterpret_cast<const float4*>(emb + (size_t)v * Ed);
    float4 w = row[threadIdx.x];
    float m = fmaxf(fmaxf(fabsf(w.x), fabsf(w.y)), fmaxf(fabsf(w.z), fabsf(w.w)));
    #pragma unroll
    for (int o = 16; o; o >>= 1) m = fmaxf(m, __shfl_xor_sync(0xffffffffu, m, o));
    __shared__ float sm[8];
    if ((threadIdx.x & 31) == 0) sm[threadIdx.x >> 5] = m;
    __syncthreads();
    if (threadIdx.x < 8) {
        m = sm[threadIdx.x];
        #pragma unroll
        for (int o = 4; o; o >>= 1) m = fmaxf(m, __shfl_xor_sync(0xffu, m, o));
        if (threadIdx.x == 0) {
            g_rowmax[v] = m;
            atomicMax(&g_maxbits, __float_as_uint(m)); // all vals >= 0: bit order == float order
        }
    }
}

// fp_quant scale: int_max = 2^(bw-1)-1 = 1 for bw=2.
__global__ void k_scale()
{
    float maxabs = __uint_as_float(g_maxbits);
    g_scale = exp2f(ceilf(log2f(maxabs)));
}

// ---------------------------------------------------------------------------
// k_signT: out[e][h] = sign(ternary(W[h][e], 0.1)). Threshold = 0.5*0.1f = 0.05f.
// which: 0=siT0, 1=siT1, 2=shT0, 3=shT1
// ---------------------------------------------------------------------------
__global__ void k_signT(const float* __restrict__ W, int which)
{
    __shared__ int8_t tile[32][33];
    int x = blockIdx.x * 32 + threadIdx.x;  // col (e)
    int y = blockIdx.y * 32 + threadIdx.y;  // row (h)
    float w = W[(size_t)y * 1024 + x];
    tile[threadIdx.y][threadIdx.x] = (w > 0.05f) ? (int8_t)1 : ((w < -0.05f) ? (int8_t)-1 : (int8_t)0);
    __syncthreads();
    int8_t* dst = (which == 0) ? g_siT0 : (which == 1) ? g_siT1 : (which == 2) ? g_shT0 : g_shT1;
    int oy = blockIdx.x * 32 + threadIdx.y; // e
    int ox = blockIdx.y * 32 + threadIdx.x; // h
    dst[(size_t)oy * 1024 + ox] = tile[threadIdx.x][threadIdx.y];
}

// ---------------------------------------------------------------------------
// k_token: per token, quantize emb row -> ternary x -> if nonzero, write
// int16 xw0 row (sum_e x_e * siT0[e][h]) and set flag bit.
// Early-exit when rowmax <= scale/2 (round-half-even makes such rows all-zero)
// or scale <= 0.5 (ternary of q*scale always 0).
// ---------------------------------------------------------------------------
__global__ void __launch_bounds__(256) k_token(const void* __restrict__ textv,
                                               const float* __restrict__ emb)
{
    int tok = blockIdx.x;                       // = b*Td + t
    long long v;
    if (g_is64) v = reinterpret_cast<const long long*>(textv)[tok];
    else        v = reinterpret_cast<const int*>(textv)[tok];
    float scale = g_scale;
    float rm = g_rowmax[v];
    if (!(scale > 0.5f) || !(rm > 0.5f * scale)) return;   // provably all-zero x row

    __shared__ int s_cnt;
    __shared__ int s_list[1024];
    if (threadIdx.x == 0) s_cnt = 0;
    __syncthreads();

    float inv = 1.0f / scale;                   // scale is a power of 2: exact
    const float4* row = reinterpret_cast<const float4*>(emb + (size_t)v * Ed);
    float4 w4 = row[threadIdx.x];
    float ws[4] = {w4.x, w4.y, w4.z, w4.w};
    int e0 = threadIdx.x * 4;
    #pragma unroll
    for (int i = 0; i < 4; i++) {
        float q = rintf(ws[i] * inv);                       // round-half-even == jnp.round
        q = fminf(fmaxf(q, -2.0f), 1.0f);                   // clip(-2, 1)
        float val = q * scale;                              // exact
        int x = (val > 0.5f) ? 1 : ((val < -0.5f) ? -1 : 0);
        if (x) { int p = atomicAdd(&s_cnt, 1); s_list[p] = ((e0 + i) << 1) | (x < 0 ? 1 : 0); }
    }
    __syncthreads();
    int cnt = s_cnt;
    if (cnt == 0) return;

    int acc[4] = {0, 0, 0, 0};
    for (int k = 0; k < cnt; k++) {
        int p = s_list[k];
        int e = p >> 1;
        int sg = (p & 1) ? -1 : 1;
        char4 c = reinterpret_cast<const char4*>(g_siT0 + (size_t)e * Hd)[threadIdx.x];
        acc[0] += sg * c.x; acc[1] += sg * c.y; acc[2] += sg * c.z; acc[3] += sg * c.w;
    }
    short4 s;
    s.x = (short)acc[0]; s.y = (short)acc[1]; s.z = (short)acc[2]; s.w = (short)acc[3];
    reinterpret_cast<short4*>(g_xw0 + (size_t)tok * Hd)[threadIdx.x] = s;
    if (threadIdx.x == 0) {
        int b = tok >> 9, t = tok & 511;
        atomicOr(&g_flags0[b * 8 + (t >> 6)], 1ull << (t & 63));
    }
}

// ---------------------------------------------------------------------------
// k_recur<LAYER>: event-driven recurrence. One block per batch element.
// 256 threads x 4 consecutive h per thread.
//   LAYER==0: PULSE input (xw row applies for one step, else 0), EMITs
//             layer-1 input rows (incrementally maintained) at h-change steps.
//   LAYER==1: HOLD input (row persists until next event), no emit.
// h_new = threshold(bias + 0.1f*(u + h . WhT)) at +-0.5 (exact reference semantics:
// tanh(+-1) thresholds back to +-1).
// If h unchanged on a non-event step, jump t to the next event bit.
// ---------------------------------------------------------------------------
__device__ __forceinline__ int next_flag(const unsigned long long* f, int t)
{
    if (t >= Td) return Td;
    int w = t >> 6;
    unsigned long long word = f[w] & (~0ull << (t & 63));
    while (true) {
        if (word) return w * 64 + __ffsll((long long)word) - 1;
        if (++w == 8) return Td;
        word = f[w];
    }
}

template <int LAYER>
__global__ void __launch_bounds__(256) k_recur(const float* __restrict__ bih,
                                               const float* __restrict__ bhh)
{
    constexpr bool PULSE = (LAYER == 0);
    constexpr bool EMIT  = (LAYER == 0);
    const unsigned long long* flagsIn = (LAYER == 0) ? g_flags0 : g_flags1;
    const short*  xw  = (LAYER == 0) ? g_xw0 : g_xw1;
    const int8_t* shT = (LAYER == 0) ? g_shT0 : g_shT1;

    int b = blockIdx.x, tid = threadIdx.x;
    __shared__ unsigned long long s_flags[8];
    __shared__ unsigned long long s_oflags[8];
    __shared__ int s_list[1024];   // nonzeros of h: (j<<1)|neg
    __shared__ int s_dlist[1024];  // changes:      (e<<3)|(delta+2)
    __shared__ int s_nl, s_nd, s_changed;

    if (tid < 8) { s_flags[tid] = flagsIn[b * 8 + tid]; s_oflags[tid] = 0ull; }
    if (tid == 0) { s_nl = 0; s_nd = 0; s_changed = 0; }

    int h0 = tid * 4;
    float bias[4];
    #pragma unroll
    for (int i = 0; i < 4; i++)
        bias[i] = bih[LAYER * Hd + h0 + i] + bhh[LAYER * Hd + h0 + i];

    int h[4] = {0, 0, 0, 0};
    int u[4] = {0, 0, 0, 0};
    int xr[4] = {0, 0, 0, 0};    // EMIT: running sum_e y_e * siT1[e][h]
    __syncthreads();

    int t = 0;
    while (t < Td) {
        bool fl = (s_flags[t >> 6] >> (t & 63)) & 1ull;
        if (fl) {
            short4 s = reinterpret_cast<const short4*>(xw + ((size_t)(b * Td + t)) * Hd)[tid];
            u[0] = s.x; u[1] = s.y; u[2] = s.z; u[3] = s.w;
        } else if (PULSE) {
            u[0] = u[1] = u[2] = u[3] = 0;
        }

        int hw[4] = {0, 0, 0, 0};
        int nl = s_nl;
        for (int k = 0; k < nl; k++) {
            int p = s_list[k];
            int j = p >> 1;
            int sg = (p & 1) ? -1 : 1;
            char4 c = reinterpret_cast<const char4*>(shT + (size_t)j * Hd)[tid];
            hw[0] += sg * c.x; hw[1] += sg * c.y; hw[2] += sg * c.z; hw[3] += sg * c.w;
        }

        int hn[4];
        #pragma unroll
        for (int i = 0; i < 4; i++) {
            float v = bias[i] + 0.1f * (float)(u[i] + hw[i]);
            hn[i] = (v > 0.5f) ? 1 : ((v < -0.5f) ? -1 : 0);
            if (hn[i] != h[i]) {
                int p = atomicAdd(&s_nd, 1);
                s_dlist[p] = ((h0 + i) << 3) | ((hn[i] - h[i]) + 2);
                s_changed = 1;
            }
        }
        __syncthreads();                              // appends visible
        int changed = s_changed, nd = s_nd;
        __syncthreads();                              // all reads done before shared is mutated

        if (changed) {
            if (EMIT) {
                for (int k = 0; k < nd; k++) {
                    int p = s_dlist[k];
                    int e = p >> 3;
                    int d = (p & 7) - 2;
                    char4 c = reinterpret_cast<const char4*>(g_siT1 + (size_t)e * Hd)[tid];
                    xr[0] += d * c.x; xr[1] += d * c.y; xr[2] += d * c.z; xr[3] += d * c.w;
                }
                short4 s;
                s.x = (short)xr[0]; s.y = (short)xr[1]; s.z = (short)xr[2]; s.w = (short)xr[3];
                reinterpret_cast<short4*>(g_xw1 + ((size_t)(b * Td + t)) * Hd)[tid] = s;
                if (tid == 0) s_oflags[t >> 6] |= 1ull << (t & 63);
            }
            if (tid == 0) s_nl = 0;
            if (tid == 1) s_nd = 0;
            if (tid == 2) s_changed = 0;
            __syncthreads();
            #pragma unroll
            for (int i = 0; i < 4; i++) {
                h[i] = hn[i];
                if (h[i]) {
                    int p = atomicAdd(&s_nl, 1);
                    s_list[p] = ((h0 + i) << 1) | (h[i] < 0 ? 1 : 0);
                }
            }
            __syncthreads();
            t += 1;
        } else {
            // h is a fixed point under current (constant) input.
            if (fl) t += 1;                // PULSE: input reverts next step -> must process it
            else    t = next_flag(s_flags, t + 1);   // safe jump: nothing changes until next event
        }
    }

    #pragma unroll
    for (int i = 0; i < 4; i++)
        g_hlast[((size_t)(LAYER * Bd + b)) * Hd + h0 + i] = (int8_t)h[i];
    if (EMIT && tid < 8) g_flags1[b * 8 + tid] = s_oflags[tid];
}

// ---------------------------------------------------------------------------
// k_fc: out[l,b,o] = sum_h h_last[l,b,h] * ternary(fc_W[o,h], 0.1)
// Sequential accumulation in h order (fp32) to mirror exact +-0.1f summation.
// ---------------------------------------------------------------------------
__global__ void k_fc(const float* __restrict__ fcW, float* __restrict__ out)
{
    int idx = threadIdx.x;              // 512 = L*B*O
    int l = idx >> 8;
    int rem = idx & 255;
    int b = rem >> 2;
    int o = rem & 3;
    const int8_t* hl = g_hlast + ((size_t)(l * Bd + b)) * Hd;
    const float* wr = fcW + (size_t)o * Hd;
    float acc = 0.0f;
    for (int hh = 0; hh < Hd; hh++) {
        int hv = hl[hh];
        if (hv) {
            float w = wr[hh];
            float fq = (w > 0.05f) ? 0.1f : ((w < -0.05f) ? -0.1f : 0.0f);
            acc += (hv > 0) ? fq : -fq;
        }
    }
    out[idx] = acc;   // idx == l*Bd*Od + b*Od + o
}

// ---------------------------------------------------------------------------
// kernel_launch
// Inputs: 0 text [B,T] (int64 or int32, detected), 1 text_lengths (unused),
//         2 emb_W [V,E], 3 W_ih [L,H,E], 4 W_hh [L,H,H], 5 b_ih [L,H],
//         6 b_hh [L,H], 7 fc_W [O,H].  Output: [L,B,O] f32.
// ---------------------------------------------------------------------------
extern "C" void kernel_launch(void* const* d_in, const int* in_sizes, int n_in,
                              void* d_out, int out_size)
{
    const void*  text = d_in[0];
    const float* emb  = (const float*)d_in[2];
    const float* Wih  = (const float*)d_in[3];
    const float* Whh  = (const float*)d_in[4];
    const float* bih  = (const float*)d_in[5];
    const float* bhh  = (const float*)d_in[6];
    const float* fcW  = (const float*)d_in[7];
    float* out = (float*)d_out;

    int V = in_sizes[2] / Ed;

    k_init<<<1, 512>>>((const int*)text);
    k_rowmax<<<V, 256>>>(emb);
    k_scale<<<1, 1>>>();

    dim3 tb(32, 32), tg(32, 32);
    k_signT<<<tg, tb>>>(Wih, 0);                          // siT0  (W_ih layer 0)
    k_signT<<<tg, tb>>>(Wih + (size_t)Hd * Ed, 1);        // siT1  (W_ih layer 1)
    k_signT<<<tg, tb>>>(Whh, 2);                          // shT0  (W_hh layer 0)
    k_signT<<<tg, tb>>>(Whh + (size_t)Hd * Hd, 3);        // shT1  (W_hh layer 1)

    k_token<<<Bd * Td, 256>>>(text, emb);

    k_recur<0><<<Bd, 256>>>(bih, bhh);
    k_recur<1><<<Bd, 256>>>(bih, bhh);

    k_fc<<<1, Ld * Bd * Od>>>(fcW, out);
}

// round 3
// speedup vs baseline: 6.7279x; 6.7279x over previous
#include <cuda_runtime.h>
#include <cstdint>

// ---------------------------------------------------------------------------
// QRNN 2-bit: ternary everything. Bit-packed popcount recurrence with
// period-1 / period-2 cycle jumping.
// Shapes: V=30000, E=H=1024, L=2, O=4, B=64, T=512.
// ---------------------------------------------------------------------------

#define Ed 1024
#define Hd 1024
#define Bd 64
#define Td 512
#define Ld 2
#define Od 4
#define VCAP 32768

// -------- device scratch (allocation-free rule: __device__ globals) --------
__device__ unsigned int       g_maxbits;
__device__ float              g_scale;
__device__ int                g_is64;              // text dtype: 1 = int64, 0 = int32
__device__ float              g_rowmax[VCAP];
// packed sign matrices: mat 0=W_ih[0], 1=W_ih[1], 2=W_hh[0], 3=W_hh[1]
// row i (output), 32 words over inputs j; bit (j&31) of word (j>>5)
__device__ uint32_t           g_packU[4 * 1024 * 32];   // nonzero mask
__device__ uint32_t           g_packS[4 * 1024 * 32];   // sign mask (1 = negative)
__device__ short              g_xw0[(size_t)Bd * Td * Hd];  // layer-0 event input rows
__device__ uint32_t           g_y[(size_t)Bd * Td * 64];    // layer-0 output masks (u[32],s[32])
__device__ unsigned long long g_flags0[Bd * 8];  // layer-0 input events
__device__ unsigned long long g_flags1[Bd * 8];  // layer-0 output-change events
__device__ int8_t             g_hlast[Ld * Bd * Hd];

// ---------------------------------------------------------------------------
__global__ void k_init(const int* __restrict__ textw)
{
    int i = threadIdx.x;
    if (i < Bd * 8) g_flags0[i] = 0ull;
    __shared__ int s_any;
    if (i == 0) { g_maxbits = 0u; s_any = 0; }
    __syncthreads();
    if (i < 64 && textw[2 * i + 1] != 0) s_any = 1;
    __syncthreads();
    if (i == 0) g_is64 = (s_any == 0) ? 1 : 0;
}

// ---------------------------------------------------------------------------
__global__ void __launch_bounds__(256) k_rowmax(const float* __restrict__ emb)
{
    int v = blockIdx.x;
    const float4* row = reinterpret_cast<const float4*>(emb + (size_t)v * Ed);
    float4 w = row[threadIdx.x];
    float m = fmaxf(fmaxf(fabsf(w.x), fabsf(w.y)), fmaxf(fabsf(w.z), fabsf(w.w)));
    #pragma unroll
    for (int o = 16; o; o >>= 1) m = fmaxf(m, __shfl_xor_sync(0xffffffffu, m, o));
    __shared__ float sm[8];
    if ((threadIdx.x & 31) == 0) sm[threadIdx.x >> 5] = m;
    __syncthreads();
    if (threadIdx.x < 8) {
        m = sm[threadIdx.x];
        #pragma unroll
        for (int o = 4; o; o >>= 1) m = fmaxf(m, __shfl_xor_sync(0xffu, m, o));
        if (threadIdx.x == 0) {
            g_rowmax[v] = m;
            atomicMax(&g_maxbits, __float_as_uint(m));
        }
    }
}

__global__ void k_scale()
{
    float maxabs = __uint_as_float(g_maxbits);
    g_scale = exp2f(ceilf(log2f(maxabs)));
}

// ---------------------------------------------------------------------------
// k_pack: one warp per weight row -> bit planes via ballot.
// ---------------------------------------------------------------------------
__global__ void __launch_bounds__(256) k_pack(const float* __restrict__ Wih,
                                              const float* __restrict__ Whh)
{
    int mat  = blockIdx.y;
    int row  = blockIdx.x * 8 + (threadIdx.x >> 5);
    int lane = threadIdx.x & 31;
    const float* W = (mat < 2) ? (Wih + (size_t)mat * 1024 * 1024)
                               : (Whh + (size_t)(mat - 2) * 1024 * 1024);
    const float* r = W + (size_t)row * 1024;
    size_t base = ((size_t)mat * 1024 + row) * 32;
    for (int w = 0; w < 32; w++) {
        float v = r[w * 32 + lane];
        unsigned bu = __ballot_sync(0xffffffffu, (v > 0.05f) || (v < -0.05f));
        unsigned bs = __ballot_sync(0xffffffffu, v < -0.05f);
        if (lane == 0) { g_packU[base + w] = bu; g_packS[base + w] = bs; }
    }
}

// ---------------------------------------------------------------------------
// k_token: per token, quantize emb row -> ternary x -> if nonzero, write
// int16 xw0 row using packed W_ih[0] bits and set the event flag.
// ---------------------------------------------------------------------------
__global__ void __launch_bounds__(256) k_token(const void* __restrict__ textv,
                                               const float* __restrict__ emb)
{
    int tok = blockIdx.x;                       // = b*Td + t
    long long v;
    if (g_is64) v = reinterpret_cast<const long long*>(textv)[tok];
    else        v = reinterpret_cast<const int*>(textv)[tok];
    float scale = g_scale;
    float rm = g_rowmax[v];
    if (!(scale > 0.5f) || !(rm > 0.5f * scale)) return;

    __shared__ int s_cnt;
    __shared__ int s_list[1024];
    if (threadIdx.x == 0) s_cnt = 0;
    __syncthreads();

    float inv = 1.0f / scale;
    const float4* row = reinterpret_cast<const float4*>(emb + (size_t)v * Ed);
    float4 w4 = row[threadIdx.x];
    float ws[4] = {w4.x, w4.y, w4.z, w4.w};
    int e0 = threadIdx.x * 4;
    #pragma unroll
    for (int i = 0; i < 4; i++) {
        float q = rintf(ws[i] * inv);
        q = fminf(fmaxf(q, -2.0f), 1.0f);
        float val = q * scale;
        int x = (val > 0.5f) ? 1 : ((val < -0.5f) ? -1 : 0);
        if (x) { int p = atomicAdd(&s_cnt, 1); s_list[p] = ((e0 + i) << 1) | (x < 0 ? 1 : 0); }
    }
    __syncthreads();
    int cnt = s_cnt;
    if (cnt == 0) return;

    int acc[4] = {0, 0, 0, 0};
    for (int k = 0; k < cnt; k++) {
        int p = s_list[k];
        int e = p >> 1;
        int sg = (p & 1) ? -1 : 1;
        int w = e >> 5;
        unsigned bm = 1u << (e & 31);
        #pragma unroll
        for (int i = 0; i < 4; i++) {
            int h = threadIdx.x * 4 + i;
            uint32_t uw = g_packU[((size_t)h) * 32 + w];   // mat 0 base offset = 0
            uint32_t sw = g_packS[((size_t)h) * 32 + w];
            if (uw & bm) acc[i] += (sw & bm) ? -sg : sg;
        }
    }
    short4 s;
    s.x = (short)acc[0]; s.y = (short)acc[1]; s.z = (short)acc[2]; s.w = (short)acc[3];
    reinterpret_cast<short4*>(g_xw0 + (size_t)tok * Hd)[threadIdx.x] = s;
    if (threadIdx.x == 0) {
        int b = tok >> 9, t = tok & 511;
        atomicOr(&g_flags0[b * 8 + (t >> 6)], 1ull << (t & 63));
    }
}

// ---------------------------------------------------------------------------
// packed ternary dot: dot = sum popc(hu&wu) - 2*sum popc(hu&wu & (hs^ws))
// ---------------------------------------------------------------------------
__device__ __forceinline__ int packed_dot(const uint32_t* hu, const uint32_t* hs,
                                          const uint32_t* __restrict__ wu,
                                          const uint32_t* __restrict__ ws)
{
    int A = 0, B = 0;
    #pragma unroll
    for (int q = 0; q < 8; q++) {
        uint4 WU = reinterpret_cast<const uint4*>(wu)[q];
        uint4 WS = reinterpret_cast<const uint4*>(ws)[q];
        uint4 HU = reinterpret_cast<const uint4*>(hu)[q];
        uint4 HS = reinterpret_cast<const uint4*>(hs)[q];
        uint32_t nz, d;
        nz = HU.x & WU.x; d = nz & (HS.x ^ WS.x); A += __popc(nz); B += __popc(d);
        nz = HU.y & WU.y; d = nz & (HS.y ^ WS.y); A += __popc(nz); B += __popc(d);
        nz = HU.z & WU.z; d = nz & (HS.z ^ WS.z); A += __popc(nz); B += __popc(d);
        nz = HU.w & WU.w; d = nz & (HS.w ^ WS.w); A += __popc(nz); B += __popc(d);
    }
    return A - 2 * B;
}

__device__ __forceinline__ int next_flag(const unsigned long long* f, int t)
{
    if (t >= Td) return Td;
    int w = t >> 6;
    unsigned long long word = f[w] & (~0ull << (t & 63));
    while (true) {
        if (word) return w * 64 + __ffsll((long long)word) - 1;
        if (++w == 8) return Td;
        word = f[w];
    }
}

// ---------------------------------------------------------------------------
// k_recur<LAYER>: one CTA (1024 threads) per batch element.
//   LAYER 0: input = pulse rows from g_xw0 (event bits g_flags0); writes y
//            masks for every t to g_y and change-bits to g_flags1.
//   LAYER 1: input = y masks (events = g_flags1), with 2-entry (mask,u) cache.
// Period-1 and period-2 cycle jumping; exact integer/float semantics match
// the validated round-1 kernel: v = bias + 0.1f*(u + dot), thresholds +-0.5.
//
// Ring-buffer invariant at the top of iteration t:
//   s_h[ic] = h_{t-1},  s_h[ip] = h_{t-2},  s_h[ip2] = h_{t-3} (write target).
// So eq2 (h_t == h_{t-2}) must compare against s_h[ip]  <-- round-2 bug was ip2.
// ---------------------------------------------------------------------------
template <int LAYER>
__global__ void __launch_bounds__(1024) k_recur(const float* __restrict__ bih,
                                                const float* __restrict__ bhh)
{
    const int b    = blockIdx.x;
    const int tid  = threadIdx.x;
    const int lane = tid & 31;
    const int wrp  = tid >> 5;             // word index 0..31

    __shared__ __align__(16) uint32_t s_h[3][64];    // [buf][word]: u 0..31, s 32..63
    __shared__ __align__(16) uint32_t s_yin[64];
    __shared__ __align__(16) uint32_t s_cm[2][64];
    __shared__ unsigned long long s_flags[8];
    __shared__ unsigned long long s_oflags[8];
    __shared__ int s_changed, s_eq2, s_mA, s_mB;

    if (tid < 64) {
        s_h[0][tid] = 0; s_h[1][tid] = 0; s_h[2][tid] = 0;
        s_yin[tid] = 0; s_cm[0][tid] = 0; s_cm[1][tid] = 0;
    }
    if (tid < 8) {
        s_flags[tid] = (LAYER == 0 ? g_flags0 : g_flags1)[b * 8 + tid];
        s_oflags[tid] = 0ull;
    }

    const uint32_t* WU = g_packU + ((size_t)((LAYER == 0 ? 2 : 3) * 1024 + tid)) * 32;
    const uint32_t* WS = g_packS + ((size_t)((LAYER == 0 ? 2 : 3) * 1024 + tid)) * 32;
    const uint32_t* XU = g_packU + ((size_t)(1 * 1024 + tid)) * 32;
    const uint32_t* XS = g_packS + ((size_t)(1 * 1024 + tid)) * 32;
    const float bias = bih[LAYER * Hd + tid] + bhh[LAYER * Hd + tid];

    int ic = 0, ip = 1, ip2 = 2;
    int u = 0, uA = 0, uB = 0, victim = 0;
    int flprev = 1;
    int t = 0;

    while (t < Td) {
        __syncthreads();                                        // (A) protect prev reads
        const int fl = (int)((s_flags[t >> 6] >> (t & 63)) & 1ull);
        if (tid == 0) { s_changed = 0; s_eq2 = 1; s_mA = 1; s_mB = 1; }
        __syncthreads();                                        // (B)

        if (LAYER == 0) {
            u = fl ? (int)g_xw0[((size_t)(b * Td + t)) * Hd + tid] : 0;
        } else if (fl) {
            if (tid < 64) {
                uint32_t ny = g_y[(((size_t)b * Td) + t) * 64 + tid];
                if (ny != s_cm[0][tid]) s_mA = 0;
                if (ny != s_cm[1][tid]) s_mB = 0;
                s_yin[tid] = ny;
            }
            __syncthreads();
            if (s_mA)      u = uA;
            else if (s_mB) u = uB;
            else {
                u = packed_dot(&s_yin[0], &s_yin[32], XU, XS);
                if (tid < 64) s_cm[victim][tid] = s_yin[tid];
                if (victim == 0) uA = u; else uB = u;
                victim ^= 1;
            }
        }

        int dot = packed_dot(&s_h[ic][0], &s_h[ic][32], WU, WS);
        float v = bias + 0.1f * (float)(u + dot);
        int hn = (v > 0.5f) ? 1 : ((v < -0.5f) ? -1 : 0);

        unsigned nu = __ballot_sync(0xffffffffu, hn != 0);
        unsigned ns = __ballot_sync(0xffffffffu, hn < 0);
        if (lane == 0) {
            uint32_t ou = s_h[ic][wrp], os = s_h[ic][32 + wrp];   // h_{t-1}
            uint32_t pu = s_h[ip][wrp], ps = s_h[ip][32 + wrp];   // h_{t-2}  (FIXED)
            if (nu != ou || ns != os) s_changed = 1;
            if (nu != pu || ns != ps) s_eq2 = 0;
            s_h[ip2][wrp] = nu; s_h[ip2][32 + wrp] = ns;
            if (LAYER == 0) {
                g_y[(((size_t)b * Td) + t) * 64 + wrp]      = nu;
                g_y[(((size_t)b * Td) + t) * 64 + 32 + wrp] = ns;
            }
        }
        __syncthreads();                                        // (C)
        const int changed = s_changed, eq2 = s_eq2;
        // rotate: ic' = h_t, ip' = h_{t-1}, ip2' = h_{t-2}
        { int n0 = ip2, n1 = ic, n2 = ip; ic = n0; ip = n1; ip2 = n2; }
        if (LAYER == 0 && changed && tid == 0)
            s_oflags[t >> 6] |= 1ull << (t & 63);

        if (changed) {
            if (eq2 && !fl && !flprev && t >= 2) {
                // established 2-cycle: ic = h_t, ip = h_{t-1}; input constant
                int te = next_flag(s_flags, t + 1);
                if (LAYER == 0) {
                    int n = (te - t - 1) * 64;
                    for (int idx = tid; idx < n; idx += 1024) {
                        int tp = t + 1 + (idx >> 6), w = idx & 63;
                        uint32_t val = ((tp - t) & 1) ? s_h[ip][w] : s_h[ic][w];
                        g_y[(((size_t)b * Td) + tp) * 64 + w] = val;
                    }
                    if (tid == 0) {   // y changes every skipped step
                        for (int w2 = 0; w2 < 8; w2++) {
                            int lo = w2 * 64;
                            int a = (t + 1 > lo) ? (t + 1) : lo;
                            int e = (te - 1 < lo + 63) ? (te - 1) : (lo + 63);
                            if (a <= e) {
                                unsigned long long m = (~0ull >> (63 - (e - lo)));
                                m &= (~0ull << (a - lo));
                                s_oflags[w2] |= m;
                            }
                        }
                    }
                }
                if (((te - 1 - t) & 1) == 1) { int sw = ic; ic = ip; ip = sw; }
                flprev = 1;
                t = te;
            } else { flprev = fl; t++; }
        } else {
            if (!fl) {
                // fixed point under constant input
                int te = next_flag(s_flags, t + 1);
                if (LAYER == 0) {
                    int n = (te - t - 1) * 64;
                    for (int idx = tid; idx < n; idx += 1024) {
                        int tp = t + 1 + (idx >> 6), w = idx & 63;
                        g_y[(((size_t)b * Td) + tp) * 64 + w] = s_h[ic][w];
                    }
                }
                flprev = 1;
                t = te;
            } else { flprev = fl; t++; }
        }
    }

    __syncthreads();
    {
        uint32_t hu = s_h[ic][wrp], hs = s_h[ic][32 + wrp];
        int nzb = (hu >> lane) & 1, sb = (hs >> lane) & 1;
        g_hlast[((size_t)(LAYER * Bd + b)) * Hd + tid] = nzb ? (sb ? (int8_t)-1 : (int8_t)1) : (int8_t)0;
    }
    if (LAYER == 0 && tid < 8) g_flags1[b * 8 + tid] = s_oflags[tid];
}

// ---------------------------------------------------------------------------
// k_fc: out[l,b,o] = sum_h h_last[l,b,h] * ternary(fc_W[o,h], 0.1)
// ---------------------------------------------------------------------------
__global__ void k_fc(const float* __restrict__ fcW, float* __restrict__ out)
{
    int idx = threadIdx.x;              // 512 = L*B*O
    int l = idx >> 8;
    int rem = idx & 255;
    int b = rem >> 2;
    int o = rem & 3;
    const int8_t* hl = g_hlast + ((size_t)(l * Bd + b)) * Hd;
    const float* wr = fcW + (size_t)o * Hd;
    float acc = 0.0f;
    for (int hh = 0; hh < Hd; hh++) {
        int hv = hl[hh];
        if (hv) {
            float w = wr[hh];
            float fq = (w > 0.05f) ? 0.1f : ((w < -0.05f) ? -0.1f : 0.0f);
            acc += (hv > 0) ? fq : -fq;
        }
    }
    out[idx] = acc;
}

// ---------------------------------------------------------------------------
extern "C" void kernel_launch(void* const* d_in, const int* in_sizes, int n_in,
                              void* d_out, int out_size)
{
    const void*  text = d_in[0];
    const float* emb  = (const float*)d_in[2];
    const float* Wih  = (const float*)d_in[3];
    const float* Whh  = (const float*)d_in[4];
    const float* bih  = (const float*)d_in[5];
    const float* bhh  = (const float*)d_in[6];
    const float* fcW  = (const float*)d_in[7];
    float* out = (float*)d_out;

    int V = in_sizes[2] / Ed;

    k_init<<<1, 512>>>((const int*)text);
    k_rowmax<<<V, 256>>>(emb);
    k_scale<<<1, 1>>>();

    k_pack<<<dim3(128, 4), 256>>>(Wih, Whh);

    k_token<<<Bd * Td, 256>>>(text, emb);

    k_recur<0><<<Bd, 1024>>>(bih, bhh);
    k_recur<1><<<Bd, 1024>>>(bih, bhh);

    k_fc<<<1, Ld * Bd * Od>>>(fcW, out);
}

// round 4
// speedup vs baseline: 22.8621x; 3.3981x over previous
#include <cuda_runtime.h>
#include <cstdint>

// ---------------------------------------------------------------------------
// QRNN 2-bit: ternary everything. Bit-packed popcount recurrence with
// coalesced [word][row] weight layout + period-1/2 cycle jumping.
// Shapes: V=30000, E=H=1024, L=2, O=4, B=64, T=512.
// ---------------------------------------------------------------------------

#define Ed 1024
#define Hd 1024
#define Bd 64
#define Td 512
#define Ld 2
#define Od 4
#define VCAP 32768

// -------- device scratch (allocation-free rule: __device__ globals) --------
__device__ unsigned int       g_maxbits;
__device__ float              g_scale;
__device__ int                g_is64;              // text dtype: 1 = int64, 0 = int32
__device__ float              g_rowmax[VCAP];
// W_ih[0] row-major planes (used only by rare k_token path)
__device__ uint32_t           g_p0U[1024 * 32];
__device__ uint32_t           g_p0S[1024 * 32];
// transposed packed mats, [mat][word][row] as uint2{u,s}:
//   mat 0 = W_ih[1], mat 1 = W_hh[0], mat 2 = W_hh[1]
__device__ uint2              g_wrUS[3 * 32 * 1024];
__device__ short              g_xw0[(size_t)Bd * Td * Hd];  // layer-0 event input rows
__device__ uint32_t           g_y[(size_t)Bd * Td * 64];    // layer-0 output masks (u[32],s[32])
__device__ unsigned long long g_flags0[Bd * 8];  // layer-0 input events
__device__ unsigned long long g_flags1[Bd * 8];  // layer-0 output-change events
__device__ int8_t             g_hlast[Ld * Bd * Hd];

// ---------------------------------------------------------------------------
__global__ void k_init(const int* __restrict__ textw)
{
    int i = threadIdx.x;
    if (i < Bd * 8) g_flags0[i] = 0ull;
    __shared__ int s_any;
    if (i == 0) { g_maxbits = 0u; s_any = 0; }
    __syncthreads();
    if (i < 64 && textw[2 * i + 1] != 0) s_any = 1;
    __syncthreads();
    if (i == 0) g_is64 = (s_any == 0) ? 1 : 0;
}

// ---------------------------------------------------------------------------
__global__ void __launch_bounds__(256) k_rowmax(const float* __restrict__ emb)
{
    int v = blockIdx.x;
    const float4* row = reinterpret_cast<const float4*>(emb + (size_t)v * Ed);
    float4 w = row[threadIdx.x];
    float m = fmaxf(fmaxf(fabsf(w.x), fabsf(w.y)), fmaxf(fabsf(w.z), fabsf(w.w)));
    #pragma unroll
    for (int o = 16; o; o >>= 1) m = fmaxf(m, __shfl_xor_sync(0xffffffffu, m, o));
    __shared__ float sm[8];
    if ((threadIdx.x & 31) == 0) sm[threadIdx.x >> 5] = m;
    __syncthreads();
    if (threadIdx.x < 8) {
        m = sm[threadIdx.x];
        #pragma unroll
        for (int o = 4; o; o >>= 1) m = fmaxf(m, __shfl_xor_sync(0xffu, m, o));
        if (threadIdx.x == 0) {
            g_rowmax[v] = m;
            atomicMax(&g_maxbits, __float_as_uint(m));
        }
    }
}

__global__ void k_scale()
{
    float maxabs = __uint_as_float(g_maxbits);
    g_scale = exp2f(ceilf(log2f(maxabs)));
}

// ---------------------------------------------------------------------------
// k_pack0: W_ih[0] -> row-major bit planes (k_token only). One warp per row.
// ---------------------------------------------------------------------------
__global__ void __launch_bounds__(256) k_pack0(const float* __restrict__ Wih)
{
    int row  = blockIdx.x * 8 + (threadIdx.x >> 5);
    int lane = threadIdx.x & 31;
    const float* r = Wih + (size_t)row * 1024;
    size_t base = (size_t)row * 32;
    for (int w = 0; w < 32; w++) {
        float v = r[w * 32 + lane];
        unsigned bu = __ballot_sync(0xffffffffu, (v > 0.05f) || (v < -0.05f));
        unsigned bs = __ballot_sync(0xffffffffu, v < -0.05f);
        if (lane == 0) { g_p0U[base + w] = bu; g_p0S[base + w] = bs; }
    }
}

// ---------------------------------------------------------------------------
// k_packT: W_ih[1], W_hh[0], W_hh[1] -> transposed [word][row] uint2 layout.
// Block = 1024 threads = 32 warps; warp wr packs row (blk*32 + wr); lane l
// keeps word l. Smem transpose tile -> fully coalesced uint2 stores.
// ---------------------------------------------------------------------------
__global__ void __launch_bounds__(1024) k_packT(const float* __restrict__ Wih,
                                                const float* __restrict__ Whh)
{
    __shared__ uint32_t tU[32][33];
    __shared__ uint32_t tS[32][33];
    int m    = blockIdx.y;                 // 0=W_ih[1], 1=W_hh[0], 2=W_hh[1]
    int blk  = blockIdx.x;                 // row block (32 rows)
    int wr   = threadIdx.x >> 5;
    int lane = threadIdx.x & 31;
    const float* W = (m == 0) ? (Wih + (size_t)1024 * 1024)
                              : (Whh + (size_t)(m - 1) * 1024 * 1024);
    const float* r = W + (size_t)(blk * 32 + wr) * 1024;

    uint32_t mu = 0, ms = 0;
    #pragma unroll
    for (int w = 0; w < 32; w++) {
        float v = r[w * 32 + lane];
        unsigned bu = __ballot_sync(0xffffffffu, (v > 0.05f) || (v < -0.05f));
        unsigned bs = __ballot_sync(0xffffffffu, v < -0.05f);
        if (lane == w) { mu = bu; ms = bs; }
    }
    tU[lane][wr] = mu;    // lane holds word index == lane for row wr
    tS[lane][wr] = ms;
    __syncthreads();

    int w = threadIdx.x >> 5;   // word
    int rr = threadIdx.x & 31;  // row-in-block
    uint2 o; o.x = tU[w][rr]; o.y = tS[w][rr];
    g_wrUS[((m * 32 + w) << 10) + blk * 32 + rr] = o;
}

// ---------------------------------------------------------------------------
// k_token: per token, quantize emb row -> ternary x -> if nonzero, write
// int16 xw0 row using row-major W_ih[0] bits and set the event flag.
// ---------------------------------------------------------------------------
__global__ void __launch_bounds__(256) k_token(const void* __restrict__ textv,
                                               const float* __restrict__ emb)
{
    int tok = blockIdx.x;                       // = b*Td + t
    long long v;
    if (g_is64) v = reinterpret_cast<const long long*>(textv)[tok];
    else        v = reinterpret_cast<const int*>(textv)[tok];
    float scale = g_scale;
    float rm = g_rowmax[v];
    if (!(scale > 0.5f) || !(rm > 0.5f * scale)) return;

    __shared__ int s_cnt;
    __shared__ int s_list[1024];
    if (threadIdx.x == 0) s_cnt = 0;
    __syncthreads();

    float inv = 1.0f / scale;
    const float4* row = reinterpret_cast<const float4*>(emb + (size_t)v * Ed);
    float4 w4 = row[threadIdx.x];
    float ws[4] = {w4.x, w4.y, w4.z, w4.w};
    int e0 = threadIdx.x * 4;
    #pragma unroll
    for (int i = 0; i < 4; i++) {
        float q = rintf(ws[i] * inv);
        q = fminf(fmaxf(q, -2.0f), 1.0f);
        float val = q * scale;
        int x = (val > 0.5f) ? 1 : ((val < -0.5f) ? -1 : 0);
        if (x) { int p = atomicAdd(&s_cnt, 1); s_list[p] = ((e0 + i) << 1) | (x < 0 ? 1 : 0); }
    }
    __syncthreads();
    int cnt = s_cnt;
    if (cnt == 0) return;

    int acc[4] = {0, 0, 0, 0};
    for (int k = 0; k < cnt; k++) {
        int p = s_list[k];
        int e = p >> 1;
        int sg = (p & 1) ? -1 : 1;
        int w = e >> 5;
        unsigned bm = 1u << (e & 31);
        #pragma unroll
        for (int i = 0; i < 4; i++) {
            int h = threadIdx.x * 4 + i;
            uint32_t uw = g_p0U[((size_t)h) * 32 + w];
            uint32_t sw = g_p0S[((size_t)h) * 32 + w];
            if (uw & bm) acc[i] += (sw & bm) ? -sg : sg;
        }
    }
    short4 s;
    s.x = (short)acc[0]; s.y = (short)acc[1]; s.z = (short)acc[2]; s.w = (short)acc[3];
    reinterpret_cast<short4*>(g_xw0 + (size_t)tok * Hd)[threadIdx.x] = s;
    if (threadIdx.x == 0) {
        int b = tok >> 9, t = tok & 511;
        atomicOr(&g_flags0[b * 8 + (t >> 6)], 1ull << (t & 63));
    }
}

// ---------------------------------------------------------------------------
// dotT: ternary dot of shared h-planes (u[0..31], s[32..63]) with transposed
// weight mat. Lane tid reads Wb[(w<<10)+tid] -> fully coalesced LDG.64.
// dot = sum popc(hu&wu) - 2*sum popc(hu&wu & (hs^ws))
// ---------------------------------------------------------------------------
__device__ __forceinline__ int dotT(const uint2* __restrict__ Wb,
                                    const uint32_t* hw, int tid)
{
    int A = 0, B = 0;
    #pragma unroll
    for (int q = 0; q < 8; q++) {
        uint4 HU = reinterpret_cast<const uint4*>(hw)[q];
        uint4 HS = reinterpret_cast<const uint4*>(hw + 32)[q];
        uint2 W; uint32_t nz, d;
        W = Wb[((q * 4 + 0) << 10) + tid]; nz = HU.x & W.x; d = nz & (HS.x ^ W.y); A += __popc(nz); B += __popc(d);
        W = Wb[((q * 4 + 1) << 10) + tid]; nz = HU.y & W.x; d = nz & (HS.y ^ W.y); A += __popc(nz); B += __popc(d);
        W = Wb[((q * 4 + 2) << 10) + tid]; nz = HU.z & W.x; d = nz & (HS.z ^ W.y); A += __popc(nz); B += __popc(d);
        W = Wb[((q * 4 + 3) << 10) + tid]; nz = HU.w & W.x; d = nz & (HS.w ^ W.y); A += __popc(nz); B += __popc(d);
    }
    return A - 2 * B;
}

__device__ __forceinline__ int next_flag(const unsigned long long* f, int t)
{
    if (t >= Td) return Td;
    int w = t >> 6;
    unsigned long long word = f[w] & (~0ull << (t & 63));
    while (true) {
        if (word) return w * 64 + __ffsll((long long)word) - 1;
        if (++w == 8) return Td;
        word = f[w];
    }
}

// ---------------------------------------------------------------------------
// k_recur<LAYER>: one CTA (1024 threads) per batch element.
//   LAYER 0: input = pulse rows from g_xw0 (event bits g_flags0); writes y
//            masks for every t to g_y and change-bits to g_flags1.
//   LAYER 1: input = y masks (events = g_flags1), with 2-entry (mask,u) cache.
// Period-1 and period-2 cycle jumping; exact float semantics preserved:
// v = bias + 0.1f*(u + dot), thresholds +-0.5.
//
// Ring-buffer invariant at the top of iteration t:
//   s_h[ic] = h_{t-1},  s_h[ip] = h_{t-2},  s_h[ip2] = h_{t-3} (write target).
// eq2 (h_t == h_{t-2}) compares against s_h[ip].
// ---------------------------------------------------------------------------
template <int LAYER>
__global__ void __launch_bounds__(1024) k_recur(const float* __restrict__ bih,
                                                const float* __restrict__ bhh)
{
    const int b    = blockIdx.x;
    const int tid  = threadIdx.x;
    const int lane = tid & 31;
    const int wrp  = tid >> 5;             // word index 0..31

    __shared__ __align__(16) uint32_t s_h[3][64];    // [buf][word]: u 0..31, s 32..63
    __shared__ __align__(16) uint32_t s_yin[64];
    __shared__ __align__(16) uint32_t s_cm[2][64];
    __shared__ unsigned long long s_flags[8];
    __shared__ unsigned long long s_oflags[8];
    __shared__ int s_changed, s_eq2, s_mA, s_mB;

    if (tid < 64) {
        s_h[0][tid] = 0; s_h[1][tid] = 0; s_h[2][tid] = 0;
        s_yin[tid] = 0; s_cm[0][tid] = 0; s_cm[1][tid] = 0;
    }
    if (tid < 8) {
        s_flags[tid] = (LAYER == 0 ? g_flags0 : g_flags1)[b * 8 + tid];
        s_oflags[tid] = 0ull;
    }

    // transposed mats: 0=W_ih[1], 1=W_hh[0], 2=W_hh[1]
    const uint2* WR = g_wrUS + ((LAYER == 0 ? 1 : 2) << 15);   // recurrent
    const uint2* XR = g_wrUS;                                  // layer-1 input (W_ih[1])
    const float bias = bih[LAYER * Hd + tid] + bhh[LAYER * Hd + tid];

    int ic = 0, ip = 1, ip2 = 2;
    int u = 0, uA = 0, uB = 0, victim = 0;
    int flprev = 1;
    int t = 0;

    while (t < Td) {
        __syncthreads();                                        // (A) protect prev reads
        const int fl = (int)((s_flags[t >> 6] >> (t & 63)) & 1ull);
        if (tid == 0) { s_changed = 0; s_eq2 = 1; s_mA = 1; s_mB = 1; }
        __syncthreads();                                        // (B)

        if (LAYER == 0) {
            u = fl ? (int)g_xw0[((size_t)(b * Td + t)) * Hd + tid] : 0;
        } else if (fl) {
            if (tid < 64) {
                uint32_t ny = g_y[(((size_t)b * Td) + t) * 64 + tid];
                if (ny != s_cm[0][tid]) s_mA = 0;
                if (ny != s_cm[1][tid]) s_mB = 0;
                s_yin[tid] = ny;
            }
            __syncthreads();
            if (s_mA)      u = uA;
            else if (s_mB) u = uB;
            else {
                u = dotT(XR, &s_yin[0], tid);
                if (tid < 64) s_cm[victim][tid] = s_yin[tid];
                if (victim == 0) uA = u; else uB = u;
                victim ^= 1;
            }
        }

        int dot = dotT(WR, &s_h[ic][0], tid);
        float v = bias + 0.1f * (float)(u + dot);
        int hn = (v > 0.5f) ? 1 : ((v < -0.5f) ? -1 : 0);

        unsigned nu = __ballot_sync(0xffffffffu, hn != 0);
        unsigned ns = __ballot_sync(0xffffffffu, hn < 0);
        if (lane == 0) {
            uint32_t ou = s_h[ic][wrp], os = s_h[ic][32 + wrp];   // h_{t-1}
            uint32_t pu = s_h[ip][wrp], ps = s_h[ip][32 + wrp];   // h_{t-2}
            if (nu != ou || ns != os) s_changed = 1;
            if (nu != pu || ns != ps) s_eq2 = 0;
            s_h[ip2][wrp] = nu; s_h[ip2][32 + wrp] = ns;
            if (LAYER == 0) {
                g_y[(((size_t)b * Td) + t) * 64 + wrp]      = nu;
                g_y[(((size_t)b * Td) + t) * 64 + 32 + wrp] = ns;
            }
        }
        __syncthreads();                                        // (C)
        const int changed = s_changed, eq2 = s_eq2;
        // rotate: ic' = h_t, ip' = h_{t-1}, ip2' = h_{t-2}
        { int n0 = ip2, n1 = ic, n2 = ip; ic = n0; ip = n1; ip2 = n2; }
        if (LAYER == 0 && changed && tid == 0)
            s_oflags[t >> 6] |= 1ull << (t & 63);

        if (changed) {
            if (eq2 && !fl && !flprev && t >= 2) {
                // established 2-cycle: ic = h_t, ip = h_{t-1}; input constant
                int te = next_flag(s_flags, t + 1);
                if (LAYER == 0) {
                    int n = (te - t - 1) * 64;
                    for (int idx = tid; idx < n; idx += 1024) {
                        int tp = t + 1 + (idx >> 6), w = idx & 63;
                        uint32_t val = ((tp - t) & 1) ? s_h[ip][w] : s_h[ic][w];
                        g_y[(((size_t)b * Td) + tp) * 64 + w] = val;
                    }
                    if (tid == 0) {   // y changes every skipped step
                        for (int w2 = 0; w2 < 8; w2++) {
                            int lo = w2 * 64;
                            int a = (t + 1 > lo) ? (t + 1) : lo;
                            int e = (te - 1 < lo + 63) ? (te - 1) : (lo + 63);
                            if (a <= e) {
                                unsigned long long msk = (~0ull >> (63 - (e - lo)));
                                msk &= (~0ull << (a - lo));
                                s_oflags[w2] |= msk;
                            }
                        }
                    }
                }
                if (((te - 1 - t) & 1) == 1) { int sw = ic; ic = ip; ip = sw; }
                flprev = 1;
                t = te;
            } else { flprev = fl; t++; }
        } else {
            if (!fl) {
                // fixed point under constant input
                int te = next_flag(s_flags, t + 1);
                if (LAYER == 0) {
                    int n = (te - t - 1) * 64;
                    for (int idx = tid; idx < n; idx += 1024) {
                        int tp = t + 1 + (idx >> 6), w = idx & 63;
                        g_y[(((size_t)b * Td) + tp) * 64 + w] = s_h[ic][w];
                    }
                }
                flprev = 1;
                t = te;
            } else { flprev = fl; t++; }
        }
    }

    __syncthreads();
    {
        uint32_t hu = s_h[ic][wrp], hs = s_h[ic][32 + wrp];
        int nzb = (hu >> lane) & 1, sb = (hs >> lane) & 1;
        g_hlast[((size_t)(LAYER * Bd + b)) * Hd + tid] = nzb ? (sb ? (int8_t)-1 : (int8_t)1) : (int8_t)0;
    }
    if (LAYER == 0 && tid < 8) g_flags1[b * 8 + tid] = s_oflags[tid];
}

// ---------------------------------------------------------------------------
// k_fc: out[l,b,o] = sum_h h_last[l,b,h] * ternary(fc_W[o,h], 0.1)
// ---------------------------------------------------------------------------
__global__ void k_fc(const float* __restrict__ fcW, float* __restrict__ out)
{
    int idx = threadIdx.x;              // 512 = L*B*O
    int l = idx >> 8;
    int rem = idx & 255;
    int b = rem >> 2;
    int o = rem & 3;
    const int8_t* hl = g_hlast + ((size_t)(l * Bd + b)) * Hd;
    const float* wr = fcW + (size_t)o * Hd;
    float acc = 0.0f;
    for (int hh = 0; hh < Hd; hh++) {
        int hv = hl[hh];
        if (hv) {
            float w = wr[hh];
            float fq = (w > 0.05f) ? 0.1f : ((w < -0.05f) ? -0.1f : 0.0f);
            acc += (hv > 0) ? fq : -fq;
        }
    }
    out[idx] = acc;
}

// ---------------------------------------------------------------------------
extern "C" void kernel_launch(void* const* d_in, const int* in_sizes, int n_in,
                              void* d_out, int out_size)
{
    const void*  text = d_in[0];
    const float* emb  = (const float*)d_in[2];
    const float* Wih  = (const float*)d_in[3];
    const float* Whh  = (const float*)d_in[4];
    const float* bih  = (const float*)d_in[5];
    const float* bhh  = (const float*)d_in[6];
    const float* fcW  = (const float*)d_in[7];
    float* out = (float*)d_out;

    int V = in_sizes[2] / Ed;

    k_init<<<1, 512>>>((const int*)text);
    k_rowmax<<<V, 256>>>(emb);
    k_scale<<<1, 1>>>();

    k_pack0<<<128, 256>>>(Wih);
    k_packT<<<dim3(32, 3), 1024>>>(Wih, Whh);

    k_token<<<Bd * Td, 256>>>(text, emb);

    k_recur<0><<<Bd, 1024>>>(bih, bhh);
    k_recur<1><<<Bd, 1024>>>(bih, bhh);

    k_fc<<<1, Ld * Bd * Od>>>(fcW, out);
}

// round 5
// speedup vs baseline: 27.5620x; 1.2056x over previous
#include <cuda_runtime.h>
#include <cstdint>

// ---------------------------------------------------------------------------
// QRNN 2-bit: ternary everything. Bit-packed popcount recurrence, 2-CTA
// cluster per batch (row-split), weights L1/smem resident, mbarrier DSMEM
// h-exchange, period-1 (fixed-point) jumping.
// Shapes: V=30000, E=H=1024, L=2, O=4, B=64, T=512.
// ---------------------------------------------------------------------------

#define Ed 1024
#define Hd 1024
#define Bd 64
#define Td 512
#define Ld 2
#define Od 4
#define VCAP 32768

// -------- device scratch (allocation-free rule: __device__ globals) --------
__device__ unsigned int       g_maxbits;
__device__ float              g_scale;
__device__ int                g_is64;              // text dtype: 1 = int64, 0 = int32
__device__ float              g_rowmax[VCAP];
// W_ih[0] row-major planes (used only by rare k_token path)
__device__ uint32_t           g_p0U[1024 * 32];
__device__ uint32_t           g_p0S[1024 * 32];
// transposed packed mats, [mat][word][row] as uint2{u,s}:
//   mat 0 = W_ih[1], mat 1 = W_hh[0], mat 2 = W_hh[1]
__device__ uint2              g_wrUS[3 * 32 * 1024];
__device__ short              g_xw0[(size_t)Bd * Td * Hd];  // layer-0 event input rows
__device__ uint32_t           g_y[(size_t)Bd * Td * 64];    // layer-0 output masks (u[32],s[32])
__device__ unsigned long long g_flags0[Bd * 8];  // layer-0 input events
__device__ unsigned long long g_flags1[Bd * 8];  // layer-0 output-change events
__device__ int8_t             g_hlast[Ld * Bd * Hd];

// ---------------- small PTX helpers ----------------------------------------
__device__ __forceinline__ uint32_t smem_u32(const void* p)
{
    uint32_t a;
    asm("{ .reg .u64 t; cvta.to.shared.u64 t, %1; cvt.u32.u64 %0, t; }" : "=r"(a) : "l"(p));
    return a;
}
__device__ __forceinline__ uint32_t mapa_u32(uint32_t a, uint32_t r)
{
    uint32_t o;
    asm("mapa.shared::cluster.u32 %0, %1, %2;" : "=r"(o) : "r"(a), "r"(r));
    return o;
}
__device__ __forceinline__ void st_cluster(uint32_t a, uint32_t v)
{
    asm volatile("st.shared::cluster.u32 [%0], %1;" :: "r"(a), "r"(v) : "memory");
}
#define MB_INIT(addr, cnt) \
    asm volatile("mbarrier.init.shared.b64 [%0], %1;" :: "r"(addr), "r"((uint32_t)(cnt)) : "memory")
#define MB_ARRIVE_LOCAL(addr) \
    asm volatile("mbarrier.arrive.shared::cta.b64 _, [%0];" :: "r"(addr) : "memory")
#define MB_ARRIVE_REMOTE_REL(addr) \
    asm volatile("mbarrier.arrive.release.cluster.shared::cluster.b64 _, [%0];" :: "r"(addr) : "memory")
#define MB_WAIT_CL(mbar, ph) do { \
    uint32_t _m = (mbar), _p = (ph), _d; \
    asm volatile("{\n\t.reg .pred p;\n\t" \
        "mbarrier.try_wait.parity.acquire.cluster.shared::cta.b64 p, [%1], %2;\n\t" \
        "selp.b32 %0, 1, 0, p;\n\t}" : "=r"(_d) : "r"(_m), "r"(_p) : "memory"); \
    if (!_d) { \
        asm volatile("{\n\t.reg .pred P1;\n\t" \
            "WL_%=:\n\t" \
            "mbarrier.try_wait.parity.acquire.cluster.shared::cta.b64 P1, [%0], %1, 0x989680;\n\t" \
            "@P1 bra.uni WD_%=;\n\t" \
            "bra.uni WL_%=;\n\t" \
            "WD_%=:\n\t}" :: "r"(_m), "r"(_p) : "memory"); \
    } } while (0)
#define CLUSTER_SYNC_() do { \
    asm volatile("barrier.cluster.arrive.aligned;" ::: "memory"); \
    asm volatile("barrier.cluster.wait.aligned;" ::: "memory"); } while (0)

// ---------------------------------------------------------------------------
__global__ void k_init(const int* __restrict__ textw)
{
    int i = threadIdx.x;
    if (i < Bd * 8) g_flags0[i] = 0ull;
    __shared__ int s_any;
    if (i == 0) { g_maxbits = 0u; s_any = 0; }
    __syncthreads();
    if (i < 64 && textw[2 * i + 1] != 0) s_any = 1;
    __syncthreads();
    if (i == 0) g_is64 = (s_any == 0) ? 1 : 0;
}

// ---------------------------------------------------------------------------
__global__ void __launch_bounds__(256) k_rowmax(const float* __restrict__ emb)
{
    int v = blockIdx.x;
    const float4* row = reinterpret_cast<const float4*>(emb + (size_t)v * Ed);
    float4 w = row[threadIdx.x];
    float m = fmaxf(fmaxf(fabsf(w.x), fabsf(w.y)), fmaxf(fabsf(w.z), fabsf(w.w)));
    #pragma unroll
    for (int o = 16; o; o >>= 1) m = fmaxf(m, __shfl_xor_sync(0xffffffffu, m, o));
    __shared__ float sm[8];
    if ((threadIdx.x & 31) == 0) sm[threadIdx.x >> 5] = m;
    __syncthreads();
    if (threadIdx.x < 8) {
        m = sm[threadIdx.x];
        #pragma unroll
        for (int o = 4; o; o >>= 1) m = fmaxf(m, __shfl_xor_sync(0xffu, m, o));
        if (threadIdx.x == 0) {
            g_rowmax[v] = m;
            atomicMax(&g_maxbits, __float_as_uint(m));
        }
    }
}

__global__ void k_scale()
{
    float maxabs = __uint_as_float(g_maxbits);
    g_scale = exp2f(ceilf(log2f(maxabs)));
}

// ---------------------------------------------------------------------------
// k_pack0: W_ih[0] -> row-major bit planes (k_token only). One warp per row.
// ---------------------------------------------------------------------------
__global__ void __launch_bounds__(256) k_pack0(const float* __restrict__ Wih)
{
    int row  = blockIdx.x * 8 + (threadIdx.x >> 5);
    int lane = threadIdx.x & 31;
    const float* r = Wih + (size_t)row * 1024;
    size_t base = (size_t)row * 32;
    for (int w = 0; w < 32; w++) {
        float v = r[w * 32 + lane];
        unsigned bu = __ballot_sync(0xffffffffu, (v > 0.05f) || (v < -0.05f));
        unsigned bs = __ballot_sync(0xffffffffu, v < -0.05f);
        if (lane == 0) { g_p0U[base + w] = bu; g_p0S[base + w] = bs; }
    }
}

// ---------------------------------------------------------------------------
// k_packT: W_ih[1], W_hh[0], W_hh[1] -> transposed [word][row] uint2 layout.
// ---------------------------------------------------------------------------
__global__ void __launch_bounds__(1024) k_packT(const float* __restrict__ Wih,
                                                const float* __restrict__ Whh)
{
    __shared__ uint32_t tU[32][33];
    __shared__ uint32_t tS[32][33];
    int m    = blockIdx.y;                 // 0=W_ih[1], 1=W_hh[0], 2=W_hh[1]
    int blk  = blockIdx.x;                 // row block (32 rows)
    int wr   = threadIdx.x >> 5;
    int lane = threadIdx.x & 31;
    const float* W = (m == 0) ? (Wih + (size_t)1024 * 1024)
                              : (Whh + (size_t)(m - 1) * 1024 * 1024);
    const float* r = W + (size_t)(blk * 32 + wr) * 1024;

    uint32_t mu = 0, ms = 0;
    #pragma unroll
    for (int w = 0; w < 32; w++) {
        float v = r[w * 32 + lane];
        unsigned bu = __ballot_sync(0xffffffffu, (v > 0.05f) || (v < -0.05f));
        unsigned bs = __ballot_sync(0xffffffffu, v < -0.05f);
        if (lane == w) { mu = bu; ms = bs; }
    }
    tU[lane][wr] = mu;
    tS[lane][wr] = ms;
    __syncthreads();

    int w = threadIdx.x >> 5;   // word
    int rr = threadIdx.x & 31;  // row-in-block
    uint2 o; o.x = tU[w][rr]; o.y = tS[w][rr];
    g_wrUS[((m * 32 + w) << 10) + blk * 32 + rr] = o;
}

// ---------------------------------------------------------------------------
// k_token: per token, quantize emb row -> ternary x -> if nonzero, write
// int16 xw0 row using row-major W_ih[0] bits and set the event flag.
// ---------------------------------------------------------------------------
__global__ void __launch_bounds__(256) k_token(const void* __restrict__ textv,
                                               const float* __restrict__ emb)
{
    int tok = blockIdx.x;                       // = b*Td + t
    long long v;
    if (g_is64) v = reinterpret_cast<const long long*>(textv)[tok];
    else        v = reinterpret_cast<const int*>(textv)[tok];
    float scale = g_scale;
    float rm = g_rowmax[v];
    if (!(scale > 0.5f) || !(rm > 0.5f * scale)) return;

    __shared__ int s_cnt;
    __shared__ int s_list[1024];
    if (threadIdx.x == 0) s_cnt = 0;
    __syncthreads();

    float inv = 1.0f / scale;
    const float4* row = reinterpret_cast<const float4*>(emb + (size_t)v * Ed);
    float4 w4 = row[threadIdx.x];
    float ws[4] = {w4.x, w4.y, w4.z, w4.w};
    int e0 = threadIdx.x * 4;
    #pragma unroll
    for (int i = 0; i < 4; i++) {
        float q = rintf(ws[i] * inv);
        q = fminf(fmaxf(q, -2.0f), 1.0f);
        float val = q * scale;
        int x = (val > 0.5f) ? 1 : ((val < -0.5f) ? -1 : 0);
        if (x) { int p = atomicAdd(&s_cnt, 1); s_list[p] = ((e0 + i) << 1) | (x < 0 ? 1 : 0); }
    }
    __syncthreads();
    int cnt = s_cnt;
    if (cnt == 0) return;

    int acc[4] = {0, 0, 0, 0};
    for (int k = 0; k < cnt; k++) {
        int p = s_list[k];
        int e = p >> 1;
        int sg = (p & 1) ? -1 : 1;
        int w = e >> 5;
        unsigned bm = 1u << (e & 31);
        #pragma unroll
        for (int i = 0; i < 4; i++) {
            int h = threadIdx.x * 4 + i;
            uint32_t uw = g_p0U[((size_t)h) * 32 + w];
            uint32_t sw = g_p0S[((size_t)h) * 32 + w];
            if (uw & bm) acc[i] += (sw & bm) ? -sg : sg;
        }
    }
    short4 s;
    s.x = (short)acc[0]; s.y = (short)acc[1]; s.z = (short)acc[2]; s.w = (short)acc[3];
    reinterpret_cast<short4*>(g_xw0 + (size_t)tok * Hd)[threadIdx.x] = s;
    if (threadIdx.x == 0) {
        int b = tok >> 9, t = tok & 511;
        atomicOr(&g_flags0[b * 8 + (t >> 6)], 1ull << (t & 63));
    }
}

// ---------------------------------------------------------------------------
// dotS<S>: ternary dot of shared h-planes (u[0..31], s[32..63]) with a weight
// column strided S uint2 per word. dot = A - 2B.
// ---------------------------------------------------------------------------
template <int S>
__device__ __forceinline__ int dotS(const uint2* __restrict__ Wp, const uint32_t* hw)
{
    int A = 0, B = 0;
    #pragma unroll
    for (int q = 0; q < 8; q++) {
        uint4 HU = reinterpret_cast<const uint4*>(hw)[q];
        uint4 HS = reinterpret_cast<const uint4*>(hw + 32)[q];
        uint2 W; uint32_t nz, d;
        W = Wp[(q * 4 + 0) * S]; nz = HU.x & W.x; d = nz & (HS.x ^ W.y); A += __popc(nz); B += __popc(d);
        W = Wp[(q * 4 + 1) * S]; nz = HU.y & W.x; d = nz & (HS.y ^ W.y); A += __popc(nz); B += __popc(d);
        W = Wp[(q * 4 + 2) * S]; nz = HU.z & W.x; d = nz & (HS.z ^ W.y); A += __popc(nz); B += __popc(d);
        W = Wp[(q * 4 + 3) * S]; nz = HU.w & W.x; d = nz & (HS.w ^ W.y); A += __popc(nz); B += __popc(d);
    }
    return A - 2 * B;
}

__device__ __forceinline__ int next_flag(const unsigned long long* f, int t)
{
    if (t >= Td) return Td;
    int w = t >> 6;
    unsigned long long word = f[w] & (~0ull << (t & 63));
    while (true) {
        if (word) return w * 64 + __ffsll((long long)word) - 1;
        if (++w == 8) return Td;
        word = f[w];
    }
}

// ---------------------------------------------------------------------------
// k_recur<LAYER>: 2-CTA cluster per batch element; CTA rank r owns rows
// [r*512, r*512+512), 512 threads, 1 row/thread. h (64 words u+s) lives in a
// 3-slot smem ring, exchanged each step via st.shared::cluster + mbarrier
// (release/acquire, cluster scope). Control flow identical across the pair.
//   LAYER 0: PULSE input from g_xw0 (events g_flags0); writes y rows (my half)
//            to g_y and change-bits to g_flags1.
//   LAYER 1: HOLD input = dot of y_t (recomputed only when flagged) with
//            W_ih[1] half staged in dynamic smem.
// Exact float semantics preserved: v = bias + 0.1f*(u + dot), thresholds +-0.5.
// ---------------------------------------------------------------------------
template <int LAYER>
__global__ void __launch_bounds__(512) __cluster_dims__(2, 1, 1)
k_recur(const float* __restrict__ bih, const float* __restrict__ bhh)
{
    extern __shared__ uint2 s_xw[];                  // LAYER 1: [32][512]
    __shared__ __align__(16) uint32_t s_buf[3][64];  // h ring: u[0..31], s[32..63]
    __shared__ __align__(16) uint32_t s_yin[64];
    __shared__ unsigned long long s_bar[3];
    __shared__ unsigned long long s_flags[8];
    __shared__ unsigned long long s_oflags[8];
    __shared__ int s_changed;

    const int      cta  = blockIdx.x;
    const int      b    = cta >> 1;
    const uint32_t rank = (uint32_t)(cta & 1);
    const uint32_t peer = rank ^ 1u;
    const int      tid  = threadIdx.x;
    const int      wid  = tid >> 5;
    const int      lane = tid & 31;
    const int      row  = (int)rank * 512 + tid;

    if (tid < 64) {
        s_buf[0][tid] = 0; s_buf[1][tid] = 0; s_buf[2][tid] = 0; s_yin[tid] = 0;
    }
    if (tid < 8) {
        s_flags[tid] = (LAYER == 0 ? g_flags0 : g_flags1)[b * 8 + tid];
        s_oflags[tid] = 0ull;
    }
    if (tid == 0) {
        s_changed = 0;
        MB_INIT(smem_u32(&s_bar[0]), 2);
        MB_INIT(smem_u32(&s_bar[1]), 2);
        MB_INIT(smem_u32(&s_bar[2]), 2);
    }

    const uint2* WR = g_wrUS + ((LAYER == 0 ? 1 : 2) << 15) + row;  // stride 1024/word
    if (LAYER == 1) {
        const uint2* X = g_wrUS;                                    // mat 0 = W_ih[1]
        for (int i = tid; i < 32 * 512; i += 512) {
            int w = i >> 9, r = i & 511;
            s_xw[i] = X[(w << 10) + (int)rank * 512 + r];
        }
    }
    const float bias = bih[LAYER * Hd + row] + bhh[LAYER * Hd + row];

    __syncthreads();
    CLUSTER_SYNC_();    // peer smem + barriers valid before any remote store

    const uint32_t myBufBase   = smem_u32(&s_buf[0][0]);
    const uint32_t peerBufBase = mapa_u32(myBufBase, peer);
    const uint32_t myBarBase   = smem_u32(&s_bar[0]);
    const uint32_t peerBarBase = mapa_u32(myBarBase, peer);

    int k = 0;                 // exchange counter; slot = k % 3
    unsigned phbits = 0;       // per-slot mbarrier phase
    int cur = 2;               // buf[(k+2)%3] holds h_{t-1}; zeroed => h0 = 0
    int u = 0;
    int t = 0;

    while (t < Td) {
        __syncthreads();                                    // (A)
        const int fl = (int)((s_flags[t >> 6] >> (t & 63)) & 1ull);
        if (tid == 0) s_changed = 0;

        if (LAYER == 0) {
            u = fl ? (int)g_xw0[((size_t)(b * Td + t)) * Hd + row] : 0;
        } else if (fl) {
            if (tid < 64) s_yin[tid] = g_y[(((size_t)b * Td) + t) * 64 + tid];
            __syncthreads();
            u = dotS<512>(s_xw + tid, s_yin);
        }

        int dot = dotS<1024>(WR, s_buf[cur]);
        float v = bias + 0.1f * (float)(u + dot);
        int hn = (v > 0.5f) ? 1 : ((v < -0.5f) ? -1 : 0);

        unsigned nu = __ballot_sync(0xffffffffu, hn != 0);
        unsigned ns = __ballot_sync(0xffffffffu, hn < 0);

        const int nxt = k - (k / 3) * 3;                    // k % 3
        const int wu  = (int)rank * 16 + wid;               // my u-word index
        if (lane == 0) {
            s_buf[nxt][wu]      = nu;
            s_buf[nxt][32 + wu] = ns;
            uint32_t ra = peerBufBase + (uint32_t)(((nxt * 64) + wu) * 4);
            st_cluster(ra,       nu);
            st_cluster(ra + 128, ns);                       // +32 words
            if (LAYER == 0) {
                g_y[(((size_t)b * Td) + t) * 64 + wu]      = nu;
                g_y[(((size_t)b * Td) + t) * 64 + 32 + wu] = ns;
            }
        }
        __syncthreads();                                    // all stores done
        if (tid == 0) {
            MB_ARRIVE_REMOTE_REL(peerBarBase + (uint32_t)(nxt * 8));
            MB_ARRIVE_LOCAL(myBarBase + (uint32_t)(nxt * 8));
        }
        MB_WAIT_CL(myBarBase + (uint32_t)(nxt * 8), (phbits >> nxt) & 1u);
        phbits ^= (1u << nxt);

        // full-h compare (identical result in both CTAs). 3-slot ring makes
        // reading buf[cur] here race-free vs the peer's future overwrites.
        if (tid < 64 && s_buf[nxt][tid] != s_buf[cur][tid]) s_changed = 1;
        __syncthreads();                                    // (C)
        const int changed = s_changed;
        k++;
        cur = nxt;                                          // buf[cur] = h_t
        if (LAYER == 0 && changed && tid == 0)
            s_oflags[t >> 6] |= 1ull << (t & 63);

        if (!changed && !fl) {
            // fixed point under constant input: jump to next event
            int te = next_flag(s_flags, t + 1);
            if (LAYER == 0) {
                int n = (te - t - 1) * 32;                  // my-half words per row
                for (int idx = tid; idx < n; idx += 512) {
                    int tp   = t + 1 + (idx >> 5);
                    int wloc = idx & 31;
                    int w = (wloc < 16) ? ((int)rank * 16 + wloc)
                                        : (32 + (int)rank * 16 + (wloc - 16));
                    g_y[(((size_t)b * Td) + tp) * 64 + w] = s_buf[cur][w];
                }
            }
            t = te;
        } else {
            t++;
        }
    }

    __syncthreads();
    {
        uint32_t hu = s_buf[cur][row >> 5];
        uint32_t hs = s_buf[cur][32 + (row >> 5)];
        int nzb = (hu >> (row & 31)) & 1, sb = (hs >> (row & 31)) & 1;
        g_hlast[((size_t)(LAYER * Bd + b)) * Hd + row] =
            nzb ? (sb ? (int8_t)-1 : (int8_t)1) : (int8_t)0;
    }
    if (LAYER == 0 && rank == 0 && tid < 8) g_flags1[b * 8 + tid] = s_oflags[tid];
    CLUSTER_SYNC_();    // no CTA exits while peer may still write our smem
}

// ---------------------------------------------------------------------------
// k_fc: out[l,b,o] = sum_h h_last[l,b,h] * ternary(fc_W[o,h], 0.1)
// ---------------------------------------------------------------------------
__global__ void k_fc(const float* __restrict__ fcW, float* __restrict__ out)
{
    int idx = threadIdx.x;              // 512 = L*B*O
    int l = idx >> 8;
    int rem = idx & 255;
    int b = rem >> 2;
    int o = rem & 3;
    const int8_t* hl = g_hlast + ((size_t)(l * Bd + b)) * Hd;
    const float* wr = fcW + (size_t)o * Hd;
    float acc = 0.0f;
    for (int hh = 0; hh < Hd; hh++) {
        int hv = hl[hh];
        if (hv) {
            float w = wr[hh];
            float fq = (w > 0.05f) ? 0.1f : ((w < -0.05f) ? -0.1f : 0.0f);
            acc += (hv > 0) ? fq : -fq;
        }
    }
    out[idx] = acc;
}

// ---------------------------------------------------------------------------
extern "C" void kernel_launch(void* const* d_in, const int* in_sizes, int n_in,
                              void* d_out, int out_size)
{
    const void*  text = d_in[0];
    const float* emb  = (const float*)d_in[2];
    const float* Wih  = (const float*)d_in[3];
    const float* Whh  = (const float*)d_in[4];
    const float* bih  = (const float*)d_in[5];
    const float* bhh  = (const float*)d_in[6];
    const float* fcW  = (const float*)d_in[7];
    float* out = (float*)d_out;

    int V = in_sizes[2] / Ed;

    cudaFuncSetAttribute(k_recur<1>, cudaFuncAttributeMaxDynamicSharedMemorySize,
                         32 * 512 * (int)sizeof(uint2));

    k_init<<<1, 512>>>((const int*)text);
    k_rowmax<<<V, 256>>>(emb);
    k_scale<<<1, 1>>>();

    k_pack0<<<128, 256>>>(Wih);
    k_packT<<<dim3(32, 3), 1024>>>(Wih, Whh);

    k_token<<<Bd * Td, 256>>>(text, emb);

    k_recur<0><<<Bd * 2, 512>>>(bih, bhh);
    k_recur<1><<<Bd * 2, 512, 32 * 512 * sizeof(uint2)>>>(bih, bhh);

    k_fc<<<1, Ld * Bd * Od>>>(fcW, out);
}

// round 6
// speedup vs baseline: 28.6230x; 1.0385x over previous
#include <cuda_runtime.h>
#include <cstdint>

// ---------------------------------------------------------------------------
// QRNN 2-bit: ternary everything. Bit-packed popcount recurrence, 2-CTA
// cluster per batch (row-split), interleaved uint4 weight layout, per-warp
// DSMEM h-exchange with a single mbarrier wait per step (no __syncthreads in
// the loop, no jump machinery -- fixed 512 steps).
// Shapes: V=30000, E=H=1024, L=2, O=4, B=64, T=512.
// ---------------------------------------------------------------------------

#define Ed 1024
#define Hd 1024
#define Bd 64
#define Td 512
#define Ld 2
#define Od 4
#define VCAP 32768

// -------- device scratch (allocation-free rule: __device__ globals) --------
__device__ unsigned int       g_maxbits;
__device__ float              g_scale;
__device__ int                g_is64;              // text dtype: 1 = int64, 0 = int32
__device__ float              g_rowmax[VCAP];
// W_ih[0] row-major planes (used only by rare k_token path)
__device__ uint32_t           g_p0U[1024 * 32];
__device__ uint32_t           g_p0S[1024 * 32];
// interleaved packed mats: g_w4[mat][wp][row] = {u(2wp), s(2wp), u(2wp+1), s(2wp+1)}
//   mat 0 = W_ih[1], mat 1 = W_hh[0], mat 2 = W_hh[1];  index ((mat*16+wp)<<10)+row
__device__ uint4              g_w4[3 * 16 * 1024];
__device__ short              g_xw0[(size_t)Bd * Td * Hd];  // layer-0 event input rows
__device__ uint4              g_y4[(size_t)Bd * Td * 16];   // layer-0 outputs, interleaved
__device__ unsigned long long g_flags0[Bd * 8];             // layer-0 input events
__device__ int8_t             g_hlast[Ld * Bd * Hd];

// ---------------- small PTX helpers ----------------------------------------
__device__ __forceinline__ uint32_t smem_u32(const void* p)
{
    uint32_t a;
    asm("{ .reg .u64 t; cvta.to.shared.u64 t, %1; cvt.u32.u64 %0, t; }" : "=r"(a) : "l"(p));
    return a;
}
__device__ __forceinline__ uint32_t mapa_u32(uint32_t a, uint32_t r)
{
    uint32_t o;
    asm("mapa.shared::cluster.u32 %0, %1, %2;" : "=r"(o) : "r"(a), "r"(r));
    return o;
}
__device__ __forceinline__ void st_cluster(uint32_t a, uint32_t v)
{
    asm volatile("st.shared::cluster.u32 [%0], %1;" :: "r"(a), "r"(v) : "memory");
}
#define MB_INIT(addr, cnt) \
    asm volatile("mbarrier.init.shared.b64 [%0], %1;" :: "r"(addr), "r"((uint32_t)(cnt)) : "memory")
#define MB_ARRIVE_LOCAL(addr) \
    asm volatile("mbarrier.arrive.release.cta.shared::cta.b64 _, [%0];" :: "r"(addr) : "memory")
#define MB_ARRIVE_REMOTE_REL(addr) \
    asm volatile("mbarrier.arrive.release.cluster.shared::cluster.b64 _, [%0];" :: "r"(addr) : "memory")
#define MB_WAIT_CL(mbar, ph) do { \
    uint32_t _m = (mbar), _p = (ph), _d; \
    asm volatile("{\n\t.reg .pred p;\n\t" \
        "mbarrier.try_wait.parity.acquire.cluster.shared::cta.b64 p, [%1], %2;\n\t" \
        "selp.b32 %0, 1, 0, p;\n\t}" : "=r"(_d) : "r"(_m), "r"(_p) : "memory"); \
    if (!_d) { \
        asm volatile("{\n\t.reg .pred P1;\n\t" \
            "WL_%=:\n\t" \
            "mbarrier.try_wait.parity.acquire.cluster.shared::cta.b64 P1, [%0], %1, 0x989680;\n\t" \
            "@P1 bra.uni WD_%=;\n\t" \
            "bra.uni WL_%=;\n\t" \
            "WD_%=:\n\t}" :: "r"(_m), "r"(_p) : "memory"); \
    } } while (0)
#define CLUSTER_SYNC_() do { \
    asm volatile("barrier.cluster.arrive.aligned;" ::: "memory"); \
    asm volatile("barrier.cluster.wait.aligned;" ::: "memory"); } while (0)

// ---------------------------------------------------------------------------
__global__ void k_init(const int* __restrict__ textw)
{
    int i = threadIdx.x;
    if (i < Bd * 8) g_flags0[i] = 0ull;
    __shared__ int s_any;
    if (i == 0) { g_maxbits = 0u; s_any = 0; }
    __syncthreads();
    if (i < 64 && textw[2 * i + 1] != 0) s_any = 1;
    __syncthreads();
    if (i == 0) g_is64 = (s_any == 0) ? 1 : 0;
}

// ---------------------------------------------------------------------------
__global__ void __launch_bounds__(256) k_rowmax(const float* __restrict__ emb)
{
    int v = blockIdx.x;
    const float4* row = reinterpret_cast<const float4*>(emb + (size_t)v * Ed);
    float4 w = row[threadIdx.x];
    float m = fmaxf(fmaxf(fabsf(w.x), fabsf(w.y)), fmaxf(fabsf(w.z), fabsf(w.w)));
    #pragma unroll
    for (int o = 16; o; o >>= 1) m = fmaxf(m, __shfl_xor_sync(0xffffffffu, m, o));
    __shared__ float sm[8];
    if ((threadIdx.x & 31) == 0) sm[threadIdx.x >> 5] = m;
    __syncthreads();
    if (threadIdx.x < 8) {
        m = sm[threadIdx.x];
        #pragma unroll
        for (int o = 4; o; o >>= 1) m = fmaxf(m, __shfl_xor_sync(0xffu, m, o));
        if (threadIdx.x == 0) {
            g_rowmax[v] = m;
            atomicMax(&g_maxbits, __float_as_uint(m));
        }
    }
}

__global__ void k_scale()
{
    float maxabs = __uint_as_float(g_maxbits);
    g_scale = exp2f(ceilf(log2f(maxabs)));
}

// ---------------------------------------------------------------------------
// k_pack0: W_ih[0] -> row-major bit planes (k_token only). One warp per row.
// ---------------------------------------------------------------------------
__global__ void __launch_bounds__(256) k_pack0(const float* __restrict__ Wih)
{
    int row  = blockIdx.x * 8 + (threadIdx.x >> 5);
    int lane = threadIdx.x & 31;
    const float* r = Wih + (size_t)row * 1024;
    size_t base = (size_t)row * 32;
    for (int w = 0; w < 32; w++) {
        float v = r[w * 32 + lane];
        unsigned bu = __ballot_sync(0xffffffffu, (v > 0.05f) || (v < -0.05f));
        unsigned bs = __ballot_sync(0xffffffffu, v < -0.05f);
        if (lane == 0) { g_p0U[base + w] = bu; g_p0S[base + w] = bs; }
    }
}

// ---------------------------------------------------------------------------
// k_packT: W_ih[1], W_hh[0], W_hh[1] -> interleaved [mat][wp][row] uint4.
// ---------------------------------------------------------------------------
__global__ void __launch_bounds__(1024) k_packT(const float* __restrict__ Wih,
                                                const float* __restrict__ Whh)
{
    __shared__ uint32_t tU[32][33];
    __shared__ uint32_t tS[32][33];
    int m    = blockIdx.y;                 // 0=W_ih[1], 1=W_hh[0], 2=W_hh[1]
    int blk  = blockIdx.x;                 // row block (32 rows)
    int wr   = threadIdx.x >> 5;
    int lane = threadIdx.x & 31;
    const float* W = (m == 0) ? (Wih + (size_t)1024 * 1024)
                              : (Whh + (size_t)(m - 1) * 1024 * 1024);
    const float* r = W + (size_t)(blk * 32 + wr) * 1024;

    uint32_t mu = 0, ms = 0;
    #pragma unroll
    for (int w = 0; w < 32; w++) {
        float v = r[w * 32 + lane];
        unsigned bu = __ballot_sync(0xffffffffu, (v > 0.05f) || (v < -0.05f));
        unsigned bs = __ballot_sync(0xffffffffu, v < -0.05f);
        if (lane == w) { mu = bu; ms = bs; }
    }
    tU[lane][wr] = mu;    // [word][rowInBlk]
    tS[lane][wr] = ms;
    __syncthreads();

    if (threadIdx.x < 512) {
        int wp = threadIdx.x >> 5;   // 0..15
        int rr = threadIdx.x & 31;
        uint4 o;
        o.x = tU[2 * wp][rr];     o.y = tS[2 * wp][rr];
        o.z = tU[2 * wp + 1][rr]; o.w = tS[2 * wp + 1][rr];
        g_w4[((m * 16 + wp) << 10) + blk * 32 + rr] = o;
    }
}

// ---------------------------------------------------------------------------
// k_token: per token, quantize emb row -> ternary x -> if nonzero, write
// int16 xw0 row using row-major W_ih[0] bits and set the event flag.
// ---------------------------------------------------------------------------
__global__ void __launch_bounds__(256) k_token(const void* __restrict__ textv,
                                               const float* __restrict__ emb)
{
    int tok = blockIdx.x;                       // = b*Td + t
    long long v;
    if (g_is64) v = reinterpret_cast<const long long*>(textv)[tok];
    else        v = reinterpret_cast<const int*>(textv)[tok];
    float scale = g_scale;
    float rm = g_rowmax[v];
    if (!(scale > 0.5f) || !(rm > 0.5f * scale)) return;

    __shared__ int s_cnt;
    __shared__ int s_list[1024];
    if (threadIdx.x == 0) s_cnt = 0;
    __syncthreads();

    float inv = 1.0f / scale;
    const float4* row = reinterpret_cast<const float4*>(emb + (size_t)v * Ed);
    float4 w4 = row[threadIdx.x];
    float ws[4] = {w4.x, w4.y, w4.z, w4.w};
    int e0 = threadIdx.x * 4;
    #pragma unroll
    for (int i = 0; i < 4; i++) {
        float q = rintf(ws[i] * inv);
        q = fminf(fmaxf(q, -2.0f), 1.0f);
        float val = q * scale;
        int x = (val > 0.5f) ? 1 : ((val < -0.5f) ? -1 : 0);
        if (x) { int p = atomicAdd(&s_cnt, 1); s_list[p] = ((e0 + i) << 1) | (x < 0 ? 1 : 0); }
    }
    __syncthreads();
    int cnt = s_cnt;
    if (cnt == 0) return;

    int acc[4] = {0, 0, 0, 0};
    for (int k = 0; k < cnt; k++) {
        int p = s_list[k];
        int e = p >> 1;
        int sg = (p & 1) ? -1 : 1;
        int w = e >> 5;
        unsigned bm = 1u << (e & 31);
        #pragma unroll
        for (int i = 0; i < 4; i++) {
            int h = threadIdx.x * 4 + i;
            uint32_t uw = g_p0U[((size_t)h) * 32 + w];
            uint32_t sw = g_p0S[((size_t)h) * 32 + w];
            if (uw & bm) acc[i] += (sw & bm) ? -sg : sg;
        }
    }
    short4 s;
    s.x = (short)acc[0]; s.y = (short)acc[1]; s.z = (short)acc[2]; s.w = (short)acc[3];
    reinterpret_cast<short4*>(g_xw0 + (size_t)tok * Hd)[threadIdx.x] = s;
    if (threadIdx.x == 0) {
        int b = tok >> 9, t = tok & 511;
        atomicOr(&g_flags0[b * 8 + (t >> 6)], 1ull << (t & 63));
    }
}

// ---------------------------------------------------------------------------
// k_recur<LAYER>: 2-CTA cluster per batch; CTA rank r owns rows
// [r*512, r*512+512), 512 threads, 1 row/thread. h lives in a 3-slot smem
// ring of interleaved uint4[16]; per-warp exchange: lane0 stores its 2 words
// locally + to the peer (st.shared::cluster), then arrives on both barriers.
// Barrier count = 32 (16 local + 16 remote warp-arrives); ONE wait per step.
// Fixed 512 steps, no divergent control flow -> lockstep by construction.
//   LAYER 0: u = pulse row from g_xw0 on event steps; writes y_t (interleaved)
//   LAYER 1: u = dot(y_t, W_ih[1]) every step (weights half staged in smem)
// Exact float semantics preserved: v = bias + 0.1f*(u + dot), thresholds +-0.5.
// ---------------------------------------------------------------------------
template <int LAYER>
__global__ void __launch_bounds__(512) __cluster_dims__(2, 1, 1)
k_recur(const float* __restrict__ bih, const float* __restrict__ bhh)
{
    extern __shared__ uint4 s_xw[];                  // LAYER 1: [16][512]
    __shared__ __align__(16) uint4 s_hb[3][16];      // h ring, interleaved
    __shared__ unsigned long long s_bar[3];
    __shared__ unsigned long long s_flags[8];

    const int      cta  = blockIdx.x;
    const int      b    = cta >> 1;
    const uint32_t rank = (uint32_t)(cta & 1);
    const uint32_t peer = rank ^ 1u;
    const int      tid  = threadIdx.x;
    const int      wid  = tid >> 5;
    const int      lane = tid & 31;
    const int      row  = (int)rank * 512 + tid;

    if (tid < 192) reinterpret_cast<uint32_t*>(s_hb)[tid] = 0;
    if (LAYER == 0 && tid < 8) s_flags[tid] = g_flags0[b * 8 + tid];
    if (tid == 0) {
        MB_INIT(smem_u32(&s_bar[0]), 32);
        MB_INIT(smem_u32(&s_bar[1]), 32);
        MB_INIT(smem_u32(&s_bar[2]), 32);
    }

    const uint4* WR = g_w4 + ((LAYER == 0 ? 1 : 2) << 14) + row;   // stride 1024/wp
    if (LAYER == 1) {
        for (int i = tid; i < 16 * 512; i += 512) {
            int wp = i >> 9, r = i & 511;
            s_xw[i] = g_w4[(wp << 10) + (int)rank * 512 + r];
        }
    }
    const float bias = bih[LAYER * Hd + row] + bhh[LAYER * Hd + row];

    __syncthreads();
    CLUSTER_SYNC_();    // peer smem + barriers valid before any remote store

    const uint32_t myBufBase   = smem_u32(&s_hb[0][0]);
    const uint32_t peerBufBase = mapa_u32(myBufBase, peer);
    const uint32_t myBarBase   = smem_u32(&s_bar[0]);
    const uint32_t peerBarBase = mapa_u32(myBarBase, peer);
    const int      w           = (int)rank * 16 + wid;       // my h word index
    const uint32_t xoff        = (uint32_t)((w >> 1) * 16 + (w & 1) * 8);

    int slot = 0;
    unsigned phbits = 0;

    for (int t = 0; t < Td; t++) {
        int rd = slot + 2; if (rd >= 3) rd -= 3;             // slot of h_{t-1}

        int u = 0;
        if (LAYER == 0) {
            int fl = (int)((s_flags[t >> 6] >> (t & 63)) & 1ull);
            if (fl) u = (int)g_xw0[((size_t)(b * Td + t)) * Hd + row];
        } else {
            const uint4* Y = g_y4 + ((size_t)b * Td + t) * 16;
            int A = 0, B = 0;
            #pragma unroll
            for (int wp = 0; wp < 16; wp++) {
                uint4 yv = __ldg(&Y[wp]);                    // uniform, L2-hit
                uint4 W4 = s_xw[(wp << 9) + tid];
                uint32_t nz0 = yv.x & W4.x, d0 = nz0 & (yv.y ^ W4.y);
                uint32_t nz1 = yv.z & W4.z, d1 = nz1 & (yv.w ^ W4.w);
                A += __popc(nz0) + __popc(nz1);
                B += __popc(d0) + __popc(d1);
            }
            u = A - 2 * B;
        }

        int A = 0, B = 0;
        #pragma unroll
        for (int wp = 0; wp < 16; wp++) {
            uint4 hv = s_hb[rd][wp];                         // broadcast LDS.128
            uint4 W4 = WR[wp << 10];                         // coalesced LDG.128
            uint32_t nz0 = hv.x & W4.x, d0 = nz0 & (hv.y ^ W4.y);
            uint32_t nz1 = hv.z & W4.z, d1 = nz1 & (hv.w ^ W4.w);
            A += __popc(nz0) + __popc(nz1);
            B += __popc(d0) + __popc(d1);
        }
        int dot = A - 2 * B;

        float v = bias + 0.1f * (float)(u + dot);
        int hn = (v > 0.5f) ? 1 : ((v < -0.5f) ? -1 : 0);
        unsigned nu = __ballot_sync(0xffffffffu, hn != 0);
        unsigned ns = __ballot_sync(0xffffffffu, hn < 0);

        if (lane == 0) {
            uint32_t* sw32 = reinterpret_cast<uint32_t*>(&s_hb[slot][0]);
            sw32[(w >> 1) * 4 + (w & 1) * 2]     = nu;
            sw32[(w >> 1) * 4 + (w & 1) * 2 + 1] = ns;
            uint32_t ra = peerBufBase + (uint32_t)(slot * 256) + xoff;
            st_cluster(ra,     nu);
            st_cluster(ra + 4, ns);
            if (LAYER == 0) {
                uint32_t* yw = reinterpret_cast<uint32_t*>(g_y4 + ((size_t)b * Td + t) * 16);
                yw[(w >> 1) * 4 + (w & 1) * 2]     = nu;
                yw[(w >> 1) * 4 + (w & 1) * 2 + 1] = ns;
            }
            MB_ARRIVE_REMOTE_REL(peerBarBase + (uint32_t)(slot * 8));
            MB_ARRIVE_LOCAL(myBarBase + (uint32_t)(slot * 8));
        }
        MB_WAIT_CL(myBarBase + (uint32_t)(slot * 8), (phbits >> slot) & 1u);
        phbits ^= (1u << slot);
        slot++; if (slot == 3) slot = 0;
    }

    {   // final h = slot written at t=511 = (slot+2)%3 now
        int ls = slot + 2; if (ls >= 3) ls -= 3;
        int myw = row >> 5;
        uint4 hv = s_hb[ls][myw >> 1];
        uint32_t hu = (myw & 1) ? hv.z : hv.x;
        uint32_t hs = (myw & 1) ? hv.w : hv.y;
        int nzb = (hu >> (row & 31)) & 1, sb = (hs >> (row & 31)) & 1;
        g_hlast[((size_t)(LAYER * Bd + b)) * Hd + row] =
            nzb ? (sb ? (int8_t)-1 : (int8_t)1) : (int8_t)0;
    }
    CLUSTER_SYNC_();    // no CTA exits while peer may still target our smem
}

// ---------------------------------------------------------------------------
// k_fc: out[l,b,o] = sum_h h_last[l,b,h] * ternary(fc_W[o,h], 0.1)
// ---------------------------------------------------------------------------
__global__ void k_fc(const float* __restrict__ fcW, float* __restrict__ out)
{
    int idx = threadIdx.x;              // 512 = L*B*O
    int l = idx >> 8;
    int rem = idx & 255;
    int b = rem >> 2;
    int o = rem & 3;
    const int8_t* hl = g_hlast + ((size_t)(l * Bd + b)) * Hd;
    const float* wr = fcW + (size_t)o * Hd;
    float acc = 0.0f;
    for (int hh = 0; hh < Hd; hh++) {
        int hv = hl[hh];
        if (hv) {
            float w = wr[hh];
            float fq = (w > 0.05f) ? 0.1f : ((w < -0.05f) ? -0.1f : 0.0f);
            acc += (hv > 0) ? fq : -fq;
        }
    }
    out[idx] = acc;
}

// ---------------------------------------------------------------------------
extern "C" void kernel_launch(void* const* d_in, const int* in_sizes, int n_in,
                              void* d_out, int out_size)
{
    const void*  text = d_in[0];
    const float* emb  = (const float*)d_in[2];
    const float* Wih  = (const float*)d_in[3];
    const float* Whh  = (const float*)d_in[4];
    const float* bih  = (const float*)d_in[5];
    const float* bhh  = (const float*)d_in[6];
    const float* fcW  = (const float*)d_in[7];
    float* out = (float*)d_out;

    int V = in_sizes[2] / Ed;

    cudaFuncSetAttribute(k_recur<1>, cudaFuncAttributeMaxDynamicSharedMemorySize,
                         16 * 512 * (int)sizeof(uint4));

    k_init<<<1, 512>>>((const int*)text);
    k_rowmax<<<V, 256>>>(emb);
    k_scale<<<1, 1>>>();

    k_pack0<<<128, 256>>>(Wih);
    k_packT<<<dim3(32, 3), 1024>>>(Wih, Whh);

    k_token<<<Bd * Td, 256>>>(text, emb);

    k_recur<0><<<Bd * 2, 512>>>(bih, bhh);
    k_recur<1><<<Bd * 2, 512, 16 * 512 * sizeof(uint4)>>>(bih, bhh);

    k_fc<<<1, Ld * Bd * Od>>>(fcW, out);
}

// round 7
// speedup vs baseline: 35.5173x; 1.2409x over previous
#include <cuda_runtime.h>
#include <cstdint>

// ---------------------------------------------------------------------------
// QRNN 2-bit: ternary everything. Bit-packed popcount recurrence, 2-CTA
// cluster per batch (row-split), recurrent weights held in REGISTERS,
// per-warp DSMEM h-exchange, exchange latency hidden under the layer-1
// input dot. Fixed 512 steps.
// Shapes: V=30000, E=H=1024, L=2, O=4, B=64, T=512.
// ---------------------------------------------------------------------------

#define Ed 1024
#define Hd 1024
#define Bd 64
#define Td 512
#define Ld 2
#define Od 4
#define VCAP 32768

// -------- device scratch (allocation-free rule: __device__ globals) --------
__device__ unsigned int       g_maxbits;
__device__ float              g_scale;
__device__ int                g_is64;              // text dtype: 1 = int64, 0 = int32
__device__ float              g_rowmax[VCAP];
// W_ih[0] row-major planes (used only by rare k_token path)
__device__ uint32_t           g_p0U[1024 * 32];
__device__ uint32_t           g_p0S[1024 * 32];
// interleaved packed mats: g_w4[mat][wp][row] = {u(2wp), s(2wp), u(2wp+1), s(2wp+1)}
//   mat 0 = W_ih[1], mat 1 = W_hh[0], mat 2 = W_hh[1];  index ((mat*16+wp)<<10)+row
__device__ uint4              g_w4[3 * 16 * 1024];
__device__ short              g_xw0[(size_t)Bd * Td * Hd];  // layer-0 event input rows
__device__ uint4              g_y4[(size_t)Bd * Td * 16];   // layer-0 outputs, interleaved
__device__ unsigned long long g_flags0[Bd * 8];             // layer-0 input events
__device__ int8_t             g_hlast[Ld * Bd * Hd];

// ---------------- small PTX helpers ----------------------------------------
__device__ __forceinline__ uint32_t smem_u32(const void* p)
{
    uint32_t a;
    asm("{ .reg .u64 t; cvta.to.shared.u64 t, %1; cvt.u32.u64 %0, t; }" : "=r"(a) : "l"(p));
    return a;
}
__device__ __forceinline__ uint32_t mapa_u32(uint32_t a, uint32_t r)
{
    uint32_t o;
    asm("mapa.shared::cluster.u32 %0, %1, %2;" : "=r"(o) : "r"(a), "r"(r));
    return o;
}
__device__ __forceinline__ void st_cluster(uint32_t a, uint32_t v)
{
    asm volatile("st.shared::cluster.u32 [%0], %1;" :: "r"(a), "r"(v) : "memory");
}
#define MB_INIT(addr, cnt) \
    asm volatile("mbarrier.init.shared.b64 [%0], %1;" :: "r"(addr), "r"((uint32_t)(cnt)) : "memory")
#define MB_ARRIVE_LOCAL(addr) \
    asm volatile("mbarrier.arrive.release.cta.shared::cta.b64 _, [%0];" :: "r"(addr) : "memory")
#define MB_ARRIVE_REMOTE_REL(addr) \
    asm volatile("mbarrier.arrive.release.cluster.shared::cluster.b64 _, [%0];" :: "r"(addr) : "memory")
#define MB_WAIT_CL(mbar, ph) do { \
    uint32_t _m = (mbar), _p = (ph), _d; \
    asm volatile("{\n\t.reg .pred p;\n\t" \
        "mbarrier.try_wait.parity.acquire.cluster.shared::cta.b64 p, [%1], %2;\n\t" \
        "selp.b32 %0, 1, 0, p;\n\t}" : "=r"(_d) : "r"(_m), "r"(_p) : "memory"); \
    if (!_d) { \
        asm volatile("{\n\t.reg .pred P1;\n\t" \
            "WL_%=:\n\t" \
            "mbarrier.try_wait.parity.acquire.cluster.shared::cta.b64 P1, [%0], %1, 0x989680;\n\t" \
            "@P1 bra.uni WD_%=;\n\t" \
            "bra.uni WL_%=;\n\t" \
            "WD_%=:\n\t}" :: "r"(_m), "r"(_p) : "memory"); \
    } } while (0)
#define CLUSTER_SYNC_() do { \
    asm volatile("barrier.cluster.arrive.aligned;" ::: "memory"); \
    asm volatile("barrier.cluster.wait.aligned;" ::: "memory"); } while (0)

// ---------------------------------------------------------------------------
__global__ void k_init(const int* __restrict__ textw)
{
    int i = threadIdx.x;
    if (i < Bd * 8) g_flags0[i] = 0ull;
    __shared__ int s_any;
    if (i == 0) { g_maxbits = 0u; s_any = 0; }
    __syncthreads();
    if (i < 64 && textw[2 * i + 1] != 0) s_any = 1;
    __syncthreads();
    if (i == 0) g_is64 = (s_any == 0) ? 1 : 0;
}

// ---------------------------------------------------------------------------
__global__ void __launch_bounds__(256) k_rowmax(const float* __restrict__ emb)
{
    int v = blockIdx.x;
    const float4* row = reinterpret_cast<const float4*>(emb + (size_t)v * Ed);
    float4 w = row[threadIdx.x];
    float m = fmaxf(fmaxf(fabsf(w.x), fabsf(w.y)), fmaxf(fabsf(w.z), fabsf(w.w)));
    #pragma unroll
    for (int o = 16; o; o >>= 1) m = fmaxf(m, __shfl_xor_sync(0xffffffffu, m, o));
    __shared__ float sm[8];
    if ((threadIdx.x & 31) == 0) sm[threadIdx.x >> 5] = m;
    __syncthreads();
    if (threadIdx.x < 8) {
        m = sm[threadIdx.x];
        #pragma unroll
        for (int o = 4; o; o >>= 1) m = fmaxf(m, __shfl_xor_sync(0xffu, m, o));
        if (threadIdx.x == 0) {
            g_rowmax[v] = m;
            atomicMax(&g_maxbits, __float_as_uint(m));
        }
    }
}

__global__ void k_scale()
{
    float maxabs = __uint_as_float(g_maxbits);
    g_scale = exp2f(ceilf(log2f(maxabs)));
}

// ---------------------------------------------------------------------------
// k_pack0: W_ih[0] -> row-major bit planes (k_token only). One warp per row.
// ---------------------------------------------------------------------------
__global__ void __launch_bounds__(256) k_pack0(const float* __restrict__ Wih)
{
    int row  = blockIdx.x * 8 + (threadIdx.x >> 5);
    int lane = threadIdx.x & 31;
    const float* r = Wih + (size_t)row * 1024;
    size_t base = (size_t)row * 32;
    for (int w = 0; w < 32; w++) {
        float v = r[w * 32 + lane];
        unsigned bu = __ballot_sync(0xffffffffu, (v > 0.05f) || (v < -0.05f));
        unsigned bs = __ballot_sync(0xffffffffu, v < -0.05f);
        if (lane == 0) { g_p0U[base + w] = bu; g_p0S[base + w] = bs; }
    }
}

// ---------------------------------------------------------------------------
// k_packT: W_ih[1], W_hh[0], W_hh[1] -> interleaved [mat][wp][row] uint4.
// ---------------------------------------------------------------------------
__global__ void __launch_bounds__(1024) k_packT(const float* __restrict__ Wih,
                                                const float* __restrict__ Whh)
{
    __shared__ uint32_t tU[32][33];
    __shared__ uint32_t tS[32][33];
    int m    = blockIdx.y;                 // 0=W_ih[1], 1=W_hh[0], 2=W_hh[1]
    int blk  = blockIdx.x;                 // row block (32 rows)
    int wr   = threadIdx.x >> 5;
    int lane = threadIdx.x & 31;
    const float* W = (m == 0) ? (Wih + (size_t)1024 * 1024)
                              : (Whh + (size_t)(m - 1) * 1024 * 1024);
    const float* r = W + (size_t)(blk * 32 + wr) * 1024;

    uint32_t mu = 0, ms = 0;
    #pragma unroll
    for (int w = 0; w < 32; w++) {
        float v = r[w * 32 + lane];
        unsigned bu = __ballot_sync(0xffffffffu, (v > 0.05f) || (v < -0.05f));
        unsigned bs = __ballot_sync(0xffffffffu, v < -0.05f);
        if (lane == w) { mu = bu; ms = bs; }
    }
    tU[lane][wr] = mu;    // [word][rowInBlk]
    tS[lane][wr] = ms;
    __syncthreads();

    if (threadIdx.x < 512) {
        int wp = threadIdx.x >> 5;   // 0..15
        int rr = threadIdx.x & 31;
        uint4 o;
        o.x = tU[2 * wp][rr];     o.y = tS[2 * wp][rr];
        o.z = tU[2 * wp + 1][rr]; o.w = tS[2 * wp + 1][rr];
        g_w4[((m * 16 + wp) << 10) + blk * 32 + rr] = o;
    }
}

// ---------------------------------------------------------------------------
// k_token: per token, quantize emb row -> ternary x -> if nonzero, write
// int16 xw0 row using row-major W_ih[0] bits and set the event flag.
// ---------------------------------------------------------------------------
__global__ void __launch_bounds__(256) k_token(const void* __restrict__ textv,
                                               const float* __restrict__ emb)
{
    int tok = blockIdx.x;                       // = b*Td + t
    long long v;
    if (g_is64) v = reinterpret_cast<const long long*>(textv)[tok];
    else        v = reinterpret_cast<const int*>(textv)[tok];
    float scale = g_scale;
    float rm = g_rowmax[v];
    if (!(scale > 0.5f) || !(rm > 0.5f * scale)) return;

    __shared__ int s_cnt;
    __shared__ int s_list[1024];
    if (threadIdx.x == 0) s_cnt = 0;
    __syncthreads();

    float inv = 1.0f / scale;
    const float4* row = reinterpret_cast<const float4*>(emb + (size_t)v * Ed);
    float4 w4 = row[threadIdx.x];
    float ws[4] = {w4.x, w4.y, w4.z, w4.w};
    int e0 = threadIdx.x * 4;
    #pragma unroll
    for (int i = 0; i < 4; i++) {
        float q = rintf(ws[i] * inv);
        q = fminf(fmaxf(q, -2.0f), 1.0f);
        float val = q * scale;
        int x = (val > 0.5f) ? 1 : ((val < -0.5f) ? -1 : 0);
        if (x) { int p = atomicAdd(&s_cnt, 1); s_list[p] = ((e0 + i) << 1) | (x < 0 ? 1 : 0); }
    }
    __syncthreads();
    int cnt = s_cnt;
    if (cnt == 0) return;

    int acc[4] = {0, 0, 0, 0};
    for (int k = 0; k < cnt; k++) {
        int p = s_list[k];
        int e = p >> 1;
        int sg = (p & 1) ? -1 : 1;
        int w = e >> 5;
        unsigned bm = 1u << (e & 31);
        #pragma unroll
        for (int i = 0; i < 4; i++) {
            int h = threadIdx.x * 4 + i;
            uint32_t uw = g_p0U[((size_t)h) * 32 + w];
            uint32_t sw = g_p0S[((size_t)h) * 32 + w];
            if (uw & bm) acc[i] += (sw & bm) ? -sg : sg;
        }
    }
    short4 s;
    s.x = (short)acc[0]; s.y = (short)acc[1]; s.z = (short)acc[2]; s.w = (short)acc[3];
    reinterpret_cast<short4*>(g_xw0 + (size_t)tok * Hd)[threadIdx.x] = s;
    if (threadIdx.x == 0) {
        int b = tok >> 9, t = tok & 511;
        atomicOr(&g_flags0[b * 8 + (t >> 6)], 1ull << (t & 63));
    }
}

// ---------------------------------------------------------------------------
// ternary dot accumulate helper on a uint4 pair (64 inputs):
//   A += popc(hu&wu) terms, B += popc(hu&wu&(hs^ws)) terms   (dot = A - 2B)
// ---------------------------------------------------------------------------
__device__ __forceinline__ void acc4(const uint4& hv, const uint4& W4, int& A, int& B)
{
    uint32_t nz0 = hv.x & W4.x, d0 = nz0 & (hv.y ^ W4.y);
    uint32_t nz1 = hv.z & W4.z, d1 = nz1 & (hv.w ^ W4.w);
    A += __popc(nz0) + __popc(nz1);
    B += __popc(d0) + __popc(d1);
}

// ---------------------------------------------------------------------------
// k_recur<LAYER>: 2-CTA cluster per batch; CTA rank r owns rows
// [r*512, r*512+512), 512 threads, 1 row/thread.
//   - Recurrent-weight column (16 x uint4 = 64 regs) held in REGISTERS.
//   - LAYER 0: u = pulse row from g_xw0 on event steps; writes y_t.
//   - LAYER 1: input-weight column also in registers; u_{t+1} (dot with
//     g_y4[t+1], no dependence on the exchange) is computed BETWEEN the
//     h_t arrives and the wait, hiding the DSMEM round-trip.
// h ring: 3 slots of interleaved uint4[16] in smem; per-warp lane0 stores
// local + peer (st.shared::cluster) then arrives on both barriers (count 32);
// one try_wait per step. Fixed 512 steps, lockstep by construction.
// Exact float semantics: v = bias + 0.1f*(u + dot), thresholds +-0.5.
// ---------------------------------------------------------------------------
template <int LAYER>
__global__ void __launch_bounds__(512) __cluster_dims__(2, 1, 1)
k_recur(const float* __restrict__ bih, const float* __restrict__ bhh)
{
    __shared__ __align__(16) uint4 s_hb[3][16];      // h ring, interleaved
    __shared__ unsigned long long s_bar[3];
    __shared__ unsigned long long s_flags[8];

    const int      cta  = blockIdx.x;
    const int      b    = cta >> 1;
    const uint32_t rank = (uint32_t)(cta & 1);
    const uint32_t peer = rank ^ 1u;
    const int      tid  = threadIdx.x;
    const int      wid  = tid >> 5;
    const int      lane = tid & 31;
    const int      row  = (int)rank * 512 + tid;

    if (tid < 192) reinterpret_cast<uint32_t*>(s_hb)[tid] = 0;
    if (LAYER == 0 && tid < 8) s_flags[tid] = g_flags0[b * 8 + tid];
    if (tid == 0) {
        MB_INIT(smem_u32(&s_bar[0]), 32);
        MB_INIT(smem_u32(&s_bar[1]), 32);
        MB_INIT(smem_u32(&s_bar[2]), 32);
    }

    // recurrent weight column -> registers (64 regs)
    uint4 wreg[16];
    {
        const uint4* WR = g_w4 + ((LAYER == 0 ? 1 : 2) << 14) + row;
        #pragma unroll
        for (int wp = 0; wp < 16; wp++) wreg[wp] = WR[wp << 10];
    }
    // layer-1 input weight column -> registers (64 regs)
    uint4 xreg[16];
    if (LAYER == 1) {
        const uint4* XR = g_w4 + row;                       // mat 0 = W_ih[1]
        #pragma unroll
        for (int wp = 0; wp < 16; wp++) xreg[wp] = XR[wp << 10];
    }
    const float bias = bih[LAYER * Hd + row] + bhh[LAYER * Hd + row];

    __syncthreads();
    CLUSTER_SYNC_();    // peer smem + barriers valid before any remote store

    const uint32_t myBufBase   = smem_u32(&s_hb[0][0]);
    const uint32_t peerBufBase = mapa_u32(myBufBase, peer);
    const uint32_t myBarBase   = smem_u32(&s_bar[0]);
    const uint32_t peerBarBase = mapa_u32(myBarBase, peer);
    const int      w           = (int)rank * 16 + wid;       // my h word index
    const uint32_t xoff        = (uint32_t)((w >> 1) * 16 + (w & 1) * 8);

    int slot = 0;
    unsigned phbits = 0;

    // layer-1: u for step 0 (y_0)
    int u_cur = 0;
    if (LAYER == 1) {
        const uint4* Y = g_y4 + (size_t)b * Td * 16;
        int A = 0, B = 0;
        #pragma unroll
        for (int wp = 0; wp < 16; wp++) acc4(Y[wp], xreg[wp], A, B);
        u_cur = A - 2 * B;
    }

    for (int t = 0; t < Td; t++) {
        int rd = slot + 2; if (rd >= 3) rd -= 3;             // slot of h_{t-1}

        int u = u_cur;
        if (LAYER == 0) {
            int fl = (int)((s_flags[t >> 6] >> (t & 63)) & 1ull);
            u = fl ? (int)g_xw0[((size_t)(b * Td + t)) * Hd + row] : 0;
        }

        int A = 0, B = 0;
        #pragma unroll
        for (int wp = 0; wp < 16; wp++) acc4(s_hb[rd][wp], wreg[wp], A, B);
        int dot = A - 2 * B;

        float v = bias + 0.1f * (float)(u + dot);
        int hn = (v > 0.5f) ? 1 : ((v < -0.5f) ? -1 : 0);
        unsigned nu = __ballot_sync(0xffffffffu, hn != 0);
        unsigned ns = __ballot_sync(0xffffffffu, hn < 0);

        if (lane == 0) {
            uint32_t* sw32 = reinterpret_cast<uint32_t*>(&s_hb[slot][0]);
            sw32[(w >> 1) * 4 + (w & 1) * 2]     = nu;
            sw32[(w >> 1) * 4 + (w & 1) * 2 + 1] = ns;
            uint32_t ra = peerBufBase + (uint32_t)(slot * 256) + xoff;
            st_cluster(ra,     nu);
            st_cluster(ra + 4, ns);
            if (LAYER == 0) {
                uint32_t* yw = reinterpret_cast<uint32_t*>(g_y4 + ((size_t)b * Td + t) * 16);
                yw[(w >> 1) * 4 + (w & 1) * 2]     = nu;
                yw[(w >> 1) * 4 + (w & 1) * 2 + 1] = ns;
            }
            MB_ARRIVE_REMOTE_REL(peerBarBase + (uint32_t)(slot * 8));
            MB_ARRIVE_LOCAL(myBarBase + (uint32_t)(slot * 8));
        }

        // overlap the exchange latency with the next-step input dot (layer 1)
        if (LAYER == 1 && t + 1 < Td) {
            const uint4* Y = g_y4 + ((size_t)b * Td + t + 1) * 16;
            int A2 = 0, B2 = 0;
            #pragma unroll
            for (int wp = 0; wp < 16; wp++) acc4(Y[wp], xreg[wp], A2, B2);
            u_cur = A2 - 2 * B2;
        }

        MB_WAIT_CL(myBarBase + (uint32_t)(slot * 8), (phbits >> slot) & 1u);
        phbits ^= (1u << slot);
        slot++; if (slot == 3) slot = 0;
    }

    {   // final h = slot written at t=511 = (slot+2)%3 now
        int ls = slot + 2; if (ls >= 3) ls -= 3;
        int myw = row >> 5;
        uint4 hv = s_hb[ls][myw >> 1];
        uint32_t hu = (myw & 1) ? hv.z : hv.x;
        uint32_t hs = (myw & 1) ? hv.w : hv.y;
        int nzb = (hu >> (row & 31)) & 1, sb = (hs >> (row & 31)) & 1;
        g_hlast[((size_t)(LAYER * Bd + b)) * Hd + row] =
            nzb ? (sb ? (int8_t)-1 : (int8_t)1) : (int8_t)0;
    }
    CLUSTER_SYNC_();    // no CTA exits while peer may still target our smem
}

// ---------------------------------------------------------------------------
// k_fc: out[l,b,o] = sum_h h_last[l,b,h] * ternary(fc_W[o,h], 0.1)
// ---------------------------------------------------------------------------
__global__ void k_fc(const float* __restrict__ fcW, float* __restrict__ out)
{
    int idx = threadIdx.x;              // 512 = L*B*O
    int l = idx >> 8;
    int rem = idx & 255;
    int b = rem >> 2;
    int o = rem & 3;
    const int8_t* hl = g_hlast + ((size_t)(l * Bd + b)) * Hd;
    const float* wr = fcW + (size_t)o * Hd;
    float acc = 0.0f;
    for (int hh = 0; hh < Hd; hh++) {
        int hv = hl[hh];
        if (hv) {
            float w = wr[hh];
            float fq = (w > 0.05f) ? 0.1f : ((w < -0.05f) ? -0.1f : 0.0f);
            acc += (hv > 0) ? fq : -fq;
        }
    }
    out[idx] = acc;
}

// ---------------------------------------------------------------------------
extern "C" void kernel_launch(void* const* d_in, const int* in_sizes, int n_in,
                              void* d_out, int out_size)
{
    const void*  text = d_in[0];
    const float* emb  = (const float*)d_in[2];
    const float* Wih  = (const float*)d_in[3];
    const float* Whh  = (const float*)d_in[4];
    const float* bih  = (const float*)d_in[5];
    const float* bhh  = (const float*)d_in[6];
    const float* fcW  = (const float*)d_in[7];
    float* out = (float*)d_out;

    int V = in_sizes[2] / Ed;

    k_init<<<1, 512>>>((const int*)text);
    k_rowmax<<<V, 256>>>(emb);
    k_scale<<<1, 1>>>();

    k_pack0<<<128, 256>>>(Wih);
    k_packT<<<dim3(32, 3), 1024>>>(Wih, Whh);

    k_token<<<Bd * Td, 256>>>(text, emb);

    k_recur<0><<<Bd * 2, 512>>>(bih, bhh);
    k_recur<1><<<Bd * 2, 512>>>(bih, bhh);

    k_fc<<<1, Ld * Bd * Od>>>(fcW, out);
}

// round 8
// speedup vs baseline: 38.8333x; 1.0934x over previous
#include <cuda_runtime.h>
#include <cstdint>

// ---------------------------------------------------------------------------
// QRNN 2-bit: ternary everything. Bit-packed popcount recurrence, 2-CTA
// cluster per batch (row-split), W_hh column in REGISTERS (both layers),
// layer-1 W_ih column in dynamic SMEM (avoids the 128-reg cap -> no spills),
// per-warp DSMEM h-exchange, exchange latency hidden under the layer-1
// input dot. Fixed 512 steps.
// Shapes: V=30000, E=H=1024, L=2, O=4, B=64, T=512.
// ---------------------------------------------------------------------------

#define Ed 1024
#define Hd 1024
#define Bd 64
#define Td 512
#define Ld 2
#define Od 4
#define VCAP 32768

// -------- device scratch (allocation-free rule: __device__ globals) --------
__device__ unsigned int       g_maxbits;
__device__ float              g_scale;
__device__ int                g_is64;              // text dtype: 1 = int64, 0 = int32
__device__ float              g_rowmax[VCAP];
// W_ih[0] row-major planes (used only by rare k_token path)
__device__ uint32_t           g_p0U[1024 * 32];
__device__ uint32_t           g_p0S[1024 * 32];
// interleaved packed mats: g_w4[mat][wp][row] = {u(2wp), s(2wp), u(2wp+1), s(2wp+1)}
//   mat 0 = W_ih[1], mat 1 = W_hh[0], mat 2 = W_hh[1];  index ((mat*16+wp)<<10)+row
__device__ uint4              g_w4[3 * 16 * 1024];
__device__ short              g_xw0[(size_t)Bd * Td * Hd];  // layer-0 event input rows
__device__ uint4              g_y4[(size_t)Bd * Td * 16];   // layer-0 outputs, interleaved
__device__ unsigned long long g_flags0[Bd * 8];             // layer-0 input events
__device__ int8_t             g_hlast[Ld * Bd * Hd];

// ---------------- small PTX helpers ----------------------------------------
__device__ __forceinline__ uint32_t smem_u32(const void* p)
{
    uint32_t a;
    asm("{ .reg .u64 t; cvta.to.shared.u64 t, %1; cvt.u32.u64 %0, t; }" : "=r"(a) : "l"(p));
    return a;
}
__device__ __forceinline__ uint32_t mapa_u32(uint32_t a, uint32_t r)
{
    uint32_t o;
    asm("mapa.shared::cluster.u32 %0, %1, %2;" : "=r"(o) : "r"(a), "r"(r));
    return o;
}
__device__ __forceinline__ void st_cluster(uint32_t a, uint32_t v)
{
    asm volatile("st.shared::cluster.u32 [%0], %1;" :: "r"(a), "r"(v) : "memory");
}
#define MB_INIT(addr, cnt) \
    asm volatile("mbarrier.init.shared.b64 [%0], %1;" :: "r"(addr), "r"((uint32_t)(cnt)) : "memory")
#define MB_ARRIVE_LOCAL(addr) \
    asm volatile("mbarrier.arrive.release.cta.shared::cta.b64 _, [%0];" :: "r"(addr) : "memory")
#define MB_ARRIVE_REMOTE_REL(addr) \
    asm volatile("mbarrier.arrive.release.cluster.shared::cluster.b64 _, [%0];" :: "r"(addr) : "memory")
#define MB_WAIT_CL(mbar, ph) do { \
    uint32_t _m = (mbar), _p = (ph), _d; \
    asm volatile("{\n\t.reg .pred p;\n\t" \
        "mbarrier.try_wait.parity.acquire.cluster.shared::cta.b64 p, [%1], %2;\n\t" \
        "selp.b32 %0, 1, 0, p;\n\t}" : "=r"(_d) : "r"(_m), "r"(_p) : "memory"); \
    if (!_d) { \
        asm volatile("{\n\t.reg .pred P1;\n\t" \
            "WL_%=:\n\t" \
            "mbarrier.try_wait.parity.acquire.cluster.shared::cta.b64 P1, [%0], %1, 0x989680;\n\t" \
            "@P1 bra.uni WD_%=;\n\t" \
            "bra.uni WL_%=;\n\t" \
            "WD_%=:\n\t}" :: "r"(_m), "r"(_p) : "memory"); \
    } } while (0)
#define CLUSTER_SYNC_() do { \
    asm volatile("barrier.cluster.arrive.aligned;" ::: "memory"); \
    asm volatile("barrier.cluster.wait.aligned;" ::: "memory"); } while (0)

// ---------------------------------------------------------------------------
__global__ void k_init(const int* __restrict__ textw)
{
    int i = threadIdx.x;
    if (i < Bd * 8) g_flags0[i] = 0ull;
    __shared__ int s_any;
    if (i == 0) { g_maxbits = 0u; s_any = 0; }
    __syncthreads();
    if (i < 64 && textw[2 * i + 1] != 0) s_any = 1;
    __syncthreads();
    if (i == 0) g_is64 = (s_any == 0) ? 1 : 0;
}

// ---------------------------------------------------------------------------
__global__ void __launch_bounds__(256) k_rowmax(const float* __restrict__ emb)
{
    int v = blockIdx.x;
    const float4* row = reinterpret_cast<const float4*>(emb + (size_t)v * Ed);
    float4 w = row[threadIdx.x];
    float m = fmaxf(fmaxf(fabsf(w.x), fabsf(w.y)), fmaxf(fabsf(w.z), fabsf(w.w)));
    #pragma unroll
    for (int o = 16; o; o >>= 1) m = fmaxf(m, __shfl_xor_sync(0xffffffffu, m, o));
    __shared__ float sm[8];
    if ((threadIdx.x & 31) == 0) sm[threadIdx.x >> 5] = m;
    __syncthreads();
    if (threadIdx.x < 8) {
        m = sm[threadIdx.x];
        #pragma unroll
        for (int o = 4; o; o >>= 1) m = fmaxf(m, __shfl_xor_sync(0xffu, m, o));
        if (threadIdx.x == 0) {
            g_rowmax[v] = m;
            atomicMax(&g_maxbits, __float_as_uint(m));
        }
    }
}

__global__ void k_scale()
{
    float maxabs = __uint_as_float(g_maxbits);
    g_scale = exp2f(ceilf(log2f(maxabs)));
}

// ---------------------------------------------------------------------------
// k_pack0: W_ih[0] -> row-major bit planes (k_token only). One warp per row.
// ---------------------------------------------------------------------------
__global__ void __launch_bounds__(256) k_pack0(const float* __restrict__ Wih)
{
    int row  = blockIdx.x * 8 + (threadIdx.x >> 5);
    int lane = threadIdx.x & 31;
    const float* r = Wih + (size_t)row * 1024;
    size_t base = (size_t)row * 32;
    for (int w = 0; w < 32; w++) {
        float v = r[w * 32 + lane];
        unsigned bu = __ballot_sync(0xffffffffu, (v > 0.05f) || (v < -0.05f));
        unsigned bs = __ballot_sync(0xffffffffu, v < -0.05f);
        if (lane == 0) { g_p0U[base + w] = bu; g_p0S[base + w] = bs; }
    }
}

// ---------------------------------------------------------------------------
// k_packT: W_ih[1], W_hh[0], W_hh[1] -> interleaved [mat][wp][row] uint4.
// ---------------------------------------------------------------------------
__global__ void __launch_bounds__(1024) k_packT(const float* __restrict__ Wih,
                                                const float* __restrict__ Whh)
{
    __shared__ uint32_t tU[32][33];
    __shared__ uint32_t tS[32][33];
    int m    = blockIdx.y;                 // 0=W_ih[1], 1=W_hh[0], 2=W_hh[1]
    int blk  = blockIdx.x;                 // row block (32 rows)
    int wr   = threadIdx.x >> 5;
    int lane = threadIdx.x & 31;
    const float* W = (m == 0) ? (Wih + (size_t)1024 * 1024)
                              : (Whh + (size_t)(m - 1) * 1024 * 1024);
    const float* r = W + (size_t)(blk * 32 + wr) * 1024;

    uint32_t mu = 0, ms = 0;
    #pragma unroll
    for (int w = 0; w < 32; w++) {
        float v = r[w * 32 + lane];
        unsigned bu = __ballot_sync(0xffffffffu, (v > 0.05f) || (v < -0.05f));
        unsigned bs = __ballot_sync(0xffffffffu, v < -0.05f);
        if (lane == w) { mu = bu; ms = bs; }
    }
    tU[lane][wr] = mu;    // [word][rowInBlk]
    tS[lane][wr] = ms;
    __syncthreads();

    if (threadIdx.x < 512) {
        int wp = threadIdx.x >> 5;   // 0..15
        int rr = threadIdx.x & 31;
        uint4 o;
        o.x = tU[2 * wp][rr];     o.y = tS[2 * wp][rr];
        o.z = tU[2 * wp + 1][rr]; o.w = tS[2 * wp + 1][rr];
        g_w4[((m * 16 + wp) << 10) + blk * 32 + rr] = o;
    }
}

// ---------------------------------------------------------------------------
// k_token: per token, quantize emb row -> ternary x -> if nonzero, write
// int16 xw0 row using row-major W_ih[0] bits and set the event flag.
// ---------------------------------------------------------------------------
__global__ void __launch_bounds__(256) k_token(const void* __restrict__ textv,
                                               const float* __restrict__ emb)
{
    int tok = blockIdx.x;                       // = b*Td + t
    long long v;
    if (g_is64) v = reinterpret_cast<const long long*>(textv)[tok];
    else        v = reinterpret_cast<const int*>(textv)[tok];
    float scale = g_scale;
    float rm = g_rowmax[v];
    if (!(scale > 0.5f) || !(rm > 0.5f * scale)) return;

    __shared__ int s_cnt;
    __shared__ int s_list[1024];
    if (threadIdx.x == 0) s_cnt = 0;
    __syncthreads();

    float inv = 1.0f / scale;
    const float4* row = reinterpret_cast<const float4*>(emb + (size_t)v * Ed);
    float4 w4 = row[threadIdx.x];
    float ws[4] = {w4.x, w4.y, w4.z, w4.w};
    int e0 = threadIdx.x * 4;
    #pragma unroll
    for (int i = 0; i < 4; i++) {
        float q = rintf(ws[i] * inv);
        q = fminf(fmaxf(q, -2.0f), 1.0f);
        float val = q * scale;
        int x = (val > 0.5f) ? 1 : ((val < -0.5f) ? -1 : 0);
        if (x) { int p = atomicAdd(&s_cnt, 1); s_list[p] = ((e0 + i) << 1) | (x < 0 ? 1 : 0); }
    }
    __syncthreads();
    int cnt = s_cnt;
    if (cnt == 0) return;

    int acc[4] = {0, 0, 0, 0};
    for (int k = 0; k < cnt; k++) {
        int p = s_list[k];
        int e = p >> 1;
        int sg = (p & 1) ? -1 : 1;
        int w = e >> 5;
        unsigned bm = 1u << (e & 31);
        #pragma unroll
        for (int i = 0; i < 4; i++) {
            int h = threadIdx.x * 4 + i;
            uint32_t uw = g_p0U[((size_t)h) * 32 + w];
            uint32_t sw = g_p0S[((size_t)h) * 32 + w];
            if (uw & bm) acc[i] += (sw & bm) ? -sg : sg;
        }
    }
    short4 s;
    s.x = (short)acc[0]; s.y = (short)acc[1]; s.z = (short)acc[2]; s.w = (short)acc[3];
    reinterpret_cast<short4*>(g_xw0 + (size_t)tok * Hd)[threadIdx.x] = s;
    if (threadIdx.x == 0) {
        int b = tok >> 9, t = tok & 511;
        atomicOr(&g_flags0[b * 8 + (t >> 6)], 1ull << (t & 63));
    }
}

// ---------------------------------------------------------------------------
// ternary dot accumulate helper on a uint4 pair (64 inputs):
//   A += popc(hu&wu) terms, B += popc(hu&wu&(hs^ws)) terms   (dot = A - 2B)
// ---------------------------------------------------------------------------
__device__ __forceinline__ void acc4(const uint4& hv, const uint4& W4, int& A, int& B)
{
    uint32_t nz0 = hv.x & W4.x, d0 = nz0 & (hv.y ^ W4.y);
    uint32_t nz1 = hv.z & W4.z, d1 = nz1 & (hv.w ^ W4.w);
    A += __popc(nz0) + __popc(nz1);
    B += __popc(d0) + __popc(d1);
}

// ---------------------------------------------------------------------------
// k_recur<LAYER>: 2-CTA cluster per batch; CTA rank r owns rows
// [r*512, r*512+512), 512 threads, 1 row/thread.
//   - Recurrent-weight column (16 x uint4 = 64 regs) in REGISTERS.
//   - LAYER 0: u = pulse row from g_xw0 on event steps; writes y_t.
//   - LAYER 1: input-weight column (W_ih[1]) staged in DYNAMIC SMEM
//     (keeps regs < the 128-reg launch_bounds cap -> no spills); u_{t+1}
//     (dot with g_y4[t+1], independent of the exchange) is computed BETWEEN
//     the h_t arrives and the wait, hiding the DSMEM round-trip.
// h ring: 3 slots of interleaved uint4[16] in smem; per-warp lane0 stores
// local + peer (st.shared::cluster) then arrives on both barriers (count 32);
// one try_wait per step. Fixed 512 steps, lockstep by construction.
// Exact float semantics: v = bias + 0.1f*(u + dot), thresholds +-0.5.
// ---------------------------------------------------------------------------
template <int LAYER>
__global__ void __launch_bounds__(512) __cluster_dims__(2, 1, 1)
k_recur(const float* __restrict__ bih, const float* __restrict__ bhh)
{
    extern __shared__ uint4 s_xw[];                  // LAYER 1: [16][512]
    __shared__ __align__(16) uint4 s_hb[3][16];      // h ring, interleaved
    __shared__ unsigned long long s_bar[3];
    __shared__ unsigned long long s_flags[8];

    const int      cta  = blockIdx.x;
    const int      b    = cta >> 1;
    const uint32_t rank = (uint32_t)(cta & 1);
    const uint32_t peer = rank ^ 1u;
    const int      tid  = threadIdx.x;
    const int      wid  = tid >> 5;
    const int      lane = tid & 31;
    const int      row  = (int)rank * 512 + tid;

    if (tid < 192) reinterpret_cast<uint32_t*>(s_hb)[tid] = 0;
    if (LAYER == 0 && tid < 8) s_flags[tid] = g_flags0[b * 8 + tid];
    if (tid == 0) {
        MB_INIT(smem_u32(&s_bar[0]), 32);
        MB_INIT(smem_u32(&s_bar[1]), 32);
        MB_INIT(smem_u32(&s_bar[2]), 32);
    }

    // recurrent weight column -> registers (64 regs)
    uint4 wreg[16];
    {
        const uint4* WR = g_w4 + ((LAYER == 0 ? 1 : 2) << 14) + row;
        #pragma unroll
        for (int wp = 0; wp < 16; wp++) wreg[wp] = WR[wp << 10];
    }
    // layer-1 input weight column -> dynamic smem (no register spills)
    if (LAYER == 1) {
        for (int i = tid; i < 16 * 512; i += 512) {
            int wp = i >> 9, r = i & 511;
            s_xw[i] = g_w4[(wp << 10) + (int)rank * 512 + r];
        }
    }
    const float bias = bih[LAYER * Hd + row] + bhh[LAYER * Hd + row];

    __syncthreads();
    CLUSTER_SYNC_();    // peer smem + barriers valid before any remote store

    const uint32_t myBufBase   = smem_u32(&s_hb[0][0]);
    const uint32_t peerBufBase = mapa_u32(myBufBase, peer);
    const uint32_t myBarBase   = smem_u32(&s_bar[0]);
    const uint32_t peerBarBase = mapa_u32(myBarBase, peer);
    const int      w           = (int)rank * 16 + wid;       // my h word index
    const uint32_t xoff        = (uint32_t)((w >> 1) * 16 + (w & 1) * 8);

    int slot = 0;
    unsigned phbits = 0;

    // layer-1: u for step 0 (y_0)
    int u_cur = 0;
    if (LAYER == 1) {
        const uint4* Y = g_y4 + (size_t)b * Td * 16;
        int A = 0, B = 0;
        #pragma unroll
        for (int wp = 0; wp < 16; wp++) acc4(__ldg(&Y[wp]), s_xw[(wp << 9) + tid], A, B);
        u_cur = A - 2 * B;
    }

    for (int t = 0; t < Td; t++) {
        int rd = slot + 2; if (rd >= 3) rd -= 3;             // slot of h_{t-1}

        int u = u_cur;
        if (LAYER == 0) {
            int fl = (int)((s_flags[t >> 6] >> (t & 63)) & 1ull);
            u = fl ? (int)g_xw0[((size_t)(b * Td + t)) * Hd + row] : 0;
        }

        int A = 0, B = 0;
        #pragma unroll
        for (int wp = 0; wp < 16; wp++) acc4(s_hb[rd][wp], wreg[wp], A, B);
        int dot = A - 2 * B;

        float v = bias + 0.1f * (float)(u + dot);
        int hn = (v > 0.5f) ? 1 : ((v < -0.5f) ? -1 : 0);
        unsigned nu = __ballot_sync(0xffffffffu, hn != 0);
        unsigned ns = __ballot_sync(0xffffffffu, hn < 0);

        if (lane == 0) {
            uint32_t* sw32 = reinterpret_cast<uint32_t*>(&s_hb[slot][0]);
            sw32[(w >> 1) * 4 + (w & 1) * 2]     = nu;
            sw32[(w >> 1) * 4 + (w & 1) * 2 + 1] = ns;
            uint32_t ra = peerBufBase + (uint32_t)(slot * 256) + xoff;
            st_cluster(ra,     nu);
            st_cluster(ra + 4, ns);
            if (LAYER == 0) {
                uint32_t* yw = reinterpret_cast<uint32_t*>(g_y4 + ((size_t)b * Td + t) * 16);
                yw[(w >> 1) * 4 + (w & 1) * 2]     = nu;
                yw[(w >> 1) * 4 + (w & 1) * 2 + 1] = ns;
            }
            MB_ARRIVE_REMOTE_REL(peerBarBase + (uint32_t)(slot * 8));
            MB_ARRIVE_LOCAL(myBarBase + (uint32_t)(slot * 8));
        }

        // overlap the exchange latency with the next-step input dot (layer 1)
        if (LAYER == 1 && t + 1 < Td) {
            const uint4* Y = g_y4 + ((size_t)b * Td + t + 1) * 16;
            int A2 = 0, B2 = 0;
            #pragma unroll
            for (int wp = 0; wp < 16; wp++) acc4(__ldg(&Y[wp]), s_xw[(wp << 9) + tid], A2, B2);
            u_cur = A2 - 2 * B2;
        }

        MB_WAIT_CL(myBarBase + (uint32_t)(slot * 8), (phbits >> slot) & 1u);
        phbits ^= (1u << slot);
        slot++; if (slot == 3) slot = 0;
    }

    {   // final h = slot written at t=511 = (slot+2)%3 now
        int ls = slot + 2; if (ls >= 3) ls -= 3;
        int myw = row >> 5;
        uint4 hv = s_hb[ls][myw >> 1];
        uint32_t hu = (myw & 1) ? hv.z : hv.x;
        uint32_t hs = (myw & 1) ? hv.w : hv.y;
        int nzb = (hu >> (row & 31)) & 1, sb = (hs >> (row & 31)) & 1;
        g_hlast[((size_t)(LAYER * Bd + b)) * Hd + row] =
            nzb ? (sb ? (int8_t)-1 : (int8_t)1) : (int8_t)0;
    }
    CLUSTER_SYNC_();    // no CTA exits while peer may still target our smem
}

// ---------------------------------------------------------------------------
// k_fc: out[l,b,o] = sum_h h_last[l,b,h] * ternary(fc_W[o,h], 0.1)
// ---------------------------------------------------------------------------
__global__ void k_fc(const float* __restrict__ fcW, float* __restrict__ out)
{
    int idx = threadIdx.x;              // 512 = L*B*O
    int l = idx >> 8;
    int rem = idx & 255;
    int b = rem >> 2;
    int o = rem & 3;
    const int8_t* hl = g_hlast + ((size_t)(l * Bd + b)) * Hd;
    const float* wr = fcW + (size_t)o * Hd;
    float acc = 0.0f;
    for (int hh = 0; hh < Hd; hh++) {
        int hv = hl[hh];
        if (hv) {
            float w = wr[hh];
            float fq = (w > 0.05f) ? 0.1f : ((w < -0.05f) ? -0.1f : 0.0f);
            acc += (hv > 0) ? fq : -fq;
        }
    }
    out[idx] = acc;
}

// ---------------------------------------------------------------------------
extern "C" void kernel_launch(void* const* d_in, const int* in_sizes, int n_in,
                              void* d_out, int out_size)
{
    const void*  text = d_in[0];
    const float* emb  = (const float*)d_in[2];
    const float* Wih  = (const float*)d_in[3];
    const float* Whh  = (const float*)d_in[4];
    const float* bih  = (const float*)d_in[5];
    const float* bhh  = (const float*)d_in[6];
    const float* fcW  = (const float*)d_in[7];
    float* out = (float*)d_out;

    int V = in_sizes[2] / Ed;

    cudaFuncSetAttribute(k_recur<1>, cudaFuncAttributeMaxDynamicSharedMemorySize,
                         16 * 512 * (int)sizeof(uint4));

    k_init<<<1, 512>>>((const int*)text);
    k_rowmax<<<V, 256>>>(emb);
    k_scale<<<1, 1>>>();

    k_pack0<<<128, 256>>>(Wih);
    k_packT<<<dim3(32, 3), 1024>>>(Wih, Whh);

    k_token<<<Bd * Td, 256>>>(text, emb);

    k_recur<0><<<Bd * 2, 512>>>(bih, bhh);
    k_recur<1><<<Bd * 2, 512, 16 * 512 * sizeof(uint4)>>>(bih, bhh);

    k_fc<<<1, Ld * Bd * Od>>>(fcW, out);
}